// round 2
// baseline (speedup 1.0000x reference)
#include <cuda_runtime.h>
#include <cuda_bf16.h>
#include <math.h>

// Problem constants
#define BB 2
#define TT 1024
#define DD 768
#define HH 12
#define HD 64
#define MM (BB*TT)     // 2048
#define FFD 3072
#define NE 4

// ---------------- scratch (static device memory; no runtime alloc) ----------
#define OFF_Q    0
#define OFF_K    (OFF_Q   + MM*DD)
#define OFF_V    (OFF_K   + MM*DD)
#define OFF_ATTN (OFF_V   + MM*DD)
#define OFF_RES1 (OFF_ATTN+ MM*DD)
#define OFF_X    (OFF_RES1+ MM*DD)
#define OFF_FF   (OFF_X   + MM*DD)
#define OFF_H    (OFF_FF  + MM*DD)
#define OFF_COMB (OFF_H   + MM*FFD)
#define BUF_TOTAL (OFF_COMB + MM*NE)

__device__ float g_buf[BUF_TOTAL];

// ---------------- block reductions ----------------
__device__ __forceinline__ float blk_reduce_sum(float v, float* red) {
    int tid = threadIdx.x;
    red[tid] = v; __syncthreads();
    for (int s = blockDim.x >> 1; s > 0; s >>= 1) {
        if (tid < s) red[tid] += red[tid + s];
        __syncthreads();
    }
    float r = red[0]; __syncthreads();
    return r;
}
__device__ __forceinline__ float blk_reduce_max(float v, float* red) {
    int tid = threadIdx.x;
    red[tid] = v; __syncthreads();
    for (int s = blockDim.x >> 1; s > 0; s >>= 1) {
        if (tid < s) red[tid] = fmaxf(red[tid], red[tid + s]);
        __syncthreads();
    }
    float r = red[0]; __syncthreads();
    return r;
}

// ---------------- generic tiled SGEMM ----------------
// C[M,N] = epi( A[M,K] @ op(B) + bias[N] )
// TRANSB: B stored [N,K] (row-major) -> C = A @ B^T   (proj weights)
//  else : B stored [K,N] (row-major) -> C = A @ B     (expert weights)
// RELU: relu after bias
// RESIDUAL: += resid[m,n]  (before store)
// WEIGHTED: C[m,n] (= or +=) rw[m*rwStride] * v   (MoE combine)
#define BM 64
#define BN 64
#define BK 16

template<bool TRANSB, bool RELU, bool WEIGHTED, bool RESIDUAL>
__global__ __launch_bounds__(256)
void gemm_k(const float* __restrict__ A, const float* __restrict__ B,
            const float* __restrict__ bias,
            const float* __restrict__ resid,
            const float* __restrict__ rw, int rwStride, int initOut,
            float* __restrict__ C, int M, int N, int K)
{
    __shared__ float As[BK][BM];
    __shared__ float Bs[BK][BN];

    const int tid = threadIdx.x;           // 256 threads
    const int bx = blockIdx.x, by = blockIdx.y;
    const int row0 = by * BM, col0 = bx * BN;
    const int tx = tid & 15, ty = tid >> 4;

    // load indices (float4 loads)
    const int lm = tid >> 2;               // 0..63
    const int lk = (tid & 3) * 4;          // 0,4,8,12
    const int bkr = tid >> 4;              // 0..15  (NN path)
    const int bnc = (tid & 15) * 4;        // 0..60  (NN path)

    float acc[4][4] = {};

    for (int k0 = 0; k0 < K; k0 += BK) {
        // A tile
        float4 av = *(const float4*)(A + (size_t)(row0 + lm) * K + k0 + lk);
        As[lk + 0][lm] = av.x; As[lk + 1][lm] = av.y;
        As[lk + 2][lm] = av.z; As[lk + 3][lm] = av.w;
        // B tile
        if (TRANSB) {
            float4 bv = *(const float4*)(B + (size_t)(col0 + lm) * K + k0 + lk);
            Bs[lk + 0][lm] = bv.x; Bs[lk + 1][lm] = bv.y;
            Bs[lk + 2][lm] = bv.z; Bs[lk + 3][lm] = bv.w;
        } else {
            float4 bv = *(const float4*)(B + (size_t)(k0 + bkr) * N + col0 + bnc);
            *(float4*)&Bs[bkr][bnc] = bv;
        }
        __syncthreads();

        #pragma unroll
        for (int kk = 0; kk < BK; kk++) {
            float4 a4 = *(const float4*)&As[kk][ty * 4];
            float4 b4 = *(const float4*)&Bs[kk][tx * 4];
            float a[4] = {a4.x, a4.y, a4.z, a4.w};
            float b[4] = {b4.x, b4.y, b4.z, b4.w};
            #pragma unroll
            for (int i = 0; i < 4; i++)
                #pragma unroll
                for (int j = 0; j < 4; j++)
                    acc[i][j] += a[i] * b[j];
        }
        __syncthreads();
    }

    #pragma unroll
    for (int i = 0; i < 4; i++) {
        const int r = row0 + ty * 4 + i;
        #pragma unroll
        for (int j = 0; j < 4; j++) {
            const int c = col0 + tx * 4 + j;
            float v = acc[i][j] + bias[c];
            if (RELU) v = fmaxf(v, 0.0f);
            if (RESIDUAL) v += resid[(size_t)r * N + c];
            if (WEIGHTED) {
                float w = rw[(size_t)r * rwStride];
                size_t idx = (size_t)r * N + c;
                if (initOut) C[idx] = w * v; else C[idx] += w * v;
            } else {
                C[(size_t)r * N + c] = v;
            }
        }
    }
}

// ---------------- attention: one block per (b,h,q) ----------------
// logits = (Q.K^T)*scale -> gamma * zscore(ddof=1, eps on std) -> softmax -> P@V
__global__ __launch_bounds__(256)
void attn_kernel(const float* __restrict__ Qb, const float* __restrict__ Kb,
                 const float* __restrict__ Vb, const float* __restrict__ gamma_p,
                 float* __restrict__ out)
{
    const int q = blockIdx.x % TT;
    const int h = (blockIdx.x / TT) % HH;
    const int b = blockIdx.x / (TT * HH);
    const int tid = threadIdx.x;  // 256

    __shared__ float qrow[HD];
    __shared__ float lg[TT];
    __shared__ float red[256];

    if (tid < HD) qrow[tid] = Qb[((size_t)(b * TT + q)) * DD + h * HD + tid];
    __syncthreads();

    float myl[4];
    #pragma unroll
    for (int r = 0; r < 4; r++) {
        const int k = tid + r * 256;
        const float4* kr = (const float4*)(Kb + ((size_t)(b * TT + k)) * DD + h * HD);
        const float4* q4 = (const float4*)qrow;
        float acc = 0.f;
        #pragma unroll
        for (int i = 0; i < 16; i++) {
            float4 kv = kr[i], qv = q4[i];
            acc += qv.x * kv.x + qv.y * kv.y + qv.z * kv.z + qv.w * kv.w;
        }
        myl[r] = acc * 0.125f;  // hd^-0.5 = 1/8
    }

    // mean
    float tot = blk_reduce_sum(myl[0] + myl[1] + myl[2] + myl[3], red);
    float mean = tot * (1.0f / TT);
    // unbiased variance (ddof=1)
    float ssl = 0.f;
    #pragma unroll
    for (int r = 0; r < 4; r++) { float d = myl[r] - mean; ssl += d * d; }
    float ss = blk_reduce_sum(ssl, red);
    float denom = sqrtf(ss * (1.0f / (TT - 1))) + 1e-5f;
    float g = *gamma_p;
    float inv = g / denom;
    #pragma unroll
    for (int r = 0; r < 4; r++) myl[r] = (myl[r] - mean) * inv;

    // softmax
    float mx = fmaxf(fmaxf(myl[0], myl[1]), fmaxf(myl[2], myl[3]));
    float gmax = blk_reduce_max(mx, red);
    float es = 0.f;
    #pragma unroll
    for (int r = 0; r < 4; r++) { myl[r] = __expf(myl[r] - gmax); es += myl[r]; }
    float Z = blk_reduce_sum(es, red);
    float rz = 1.0f / Z;
    #pragma unroll
    for (int r = 0; r < 4; r++) lg[tid + r * 256] = myl[r] * rz;
    __syncthreads();

    // P@V : thread (c=tid>>6, d=tid&63) handles k-chunk c over column d
    const int d = tid & 63, c = tid >> 6;
    float acc = 0.f;
    const float* vb = Vb + ((size_t)(b * TT + c * 256)) * DD + h * HD + d;
    const float* pp = &lg[c * 256];
    for (int k = 0; k < 256; k++) acc += pp[k] * vb[(size_t)k * DD];
    red[tid] = acc;
    __syncthreads();
    if (tid < 64) {
        float o = red[tid] + red[tid + 64] + red[tid + 128] + red[tid + 192];
        out[((size_t)(b * TT + q)) * DD + h * HD + tid] = o;
    }
}

// ---------------- layernorm over rows of D=768 ----------------
// out = LN(in + add) * g + b ; add nullable
__global__ __launch_bounds__(256)
void ln_kernel(const float* __restrict__ in, const float* __restrict__ add,
               const float* __restrict__ gw, const float* __restrict__ bw,
               float* __restrict__ out)
{
    const int row = blockIdx.x;
    const int tid = threadIdx.x;  // 256, 3 elems each
    __shared__ float red[256];

    float v[3];
    #pragma unroll
    for (int i = 0; i < 3; i++) {
        int c = tid + i * 256;
        size_t idx = (size_t)row * DD + c;
        v[i] = in[idx] + (add ? add[idx] : 0.0f);
    }
    float tot = blk_reduce_sum(v[0] + v[1] + v[2], red);
    float mean = tot * (1.0f / DD);
    float s2 = 0.f;
    #pragma unroll
    for (int i = 0; i < 3; i++) { float d = v[i] - mean; s2 += d * d; }
    float var = blk_reduce_sum(s2, red) * (1.0f / DD);
    float rstd = rsqrtf(var + 1e-5f);
    #pragma unroll
    for (int i = 0; i < 3; i++) {
        int c = tid + i * 256;
        out[(size_t)row * DD + c] = (v[i] - mean) * rstd * gw[c] + bw[c];
    }
}

// ---------------- gate: softmax(x@Wg^T+bg) -> top2 combine weights ----------
__global__ __launch_bounds__(128)
void gate_kernel(const float* __restrict__ x, const float* __restrict__ Wg,
                 const float* __restrict__ bg, float* __restrict__ comb)
{
    const int row = blockIdx.x;
    const int tid = threadIdx.x; // 128
    float acc[NE] = {};
    for (int d = tid; d < DD; d += 128) {
        float xv = x[(size_t)row * DD + d];
        #pragma unroll
        for (int e = 0; e < NE; e++) acc[e] += xv * Wg[e * DD + d];
    }
    __shared__ float red[NE][128];
    #pragma unroll
    for (int e = 0; e < NE; e++) red[e][tid] = acc[e];
    __syncthreads();
    for (int s = 64; s > 0; s >>= 1) {
        if (tid < s) {
            #pragma unroll
            for (int e = 0; e < NE; e++) red[e][tid] += red[e][tid + s];
        }
        __syncthreads();
    }
    if (tid == 0) {
        float sc[NE];
        #pragma unroll
        for (int e = 0; e < NE; e++) sc[e] = red[e][0] + bg[e];
        float m = sc[0];
        #pragma unroll
        for (int e = 1; e < NE; e++) m = fmaxf(m, sc[e]);
        float p[NE], Z = 0.f;
        #pragma unroll
        for (int e = 0; e < NE; e++) { p[e] = __expf(sc[e] - m); Z += p[e]; }
        #pragma unroll
        for (int e = 0; e < NE; e++) p[e] /= Z;
        // top-2, first-index tie-break (strict >)
        int i1 = 0;
        for (int e = 1; e < NE; e++) if (p[e] > p[i1]) i1 = e;
        int i2 = -1;
        for (int e = 0; e < NE; e++) {
            if (e == i1) continue;
            if (i2 < 0 || p[e] > p[i2]) i2 = e;
        }
        #pragma unroll
        for (int e = 0; e < NE; e++)
            comb[(size_t)row * NE + e] = (e == i1 || e == i2) ? p[e] : 0.0f;
    }
}

// ---------------- launcher ----------------
extern "C" void kernel_launch(void* const* d_in, const int* in_sizes, int n_in,
                              void* d_out, int out_size)
{
    (void)in_sizes; (void)n_in; (void)out_size;
    const float* src   = (const float*)d_in[0];
    // d_in[1] = frac (unused in this reference path)
    const float* Wq    = (const float*)d_in[2];
    const float* bq    = (const float*)d_in[3];
    const float* Wk    = (const float*)d_in[4];
    const float* bk    = (const float*)d_in[5];
    const float* Wv    = (const float*)d_in[6];
    const float* bv    = (const float*)d_in[7];
    const float* Wo    = (const float*)d_in[8];
    const float* bo    = (const float*)d_in[9];
    const float* gamma = (const float*)d_in[10];
    const float* ln1g  = (const float*)d_in[11];
    const float* ln1b  = (const float*)d_in[12];
    const float* ln2g  = (const float*)d_in[13];
    const float* ln2b  = (const float*)d_in[14];
    const float* Wg    = (const float*)d_in[15];
    const float* bg    = (const float*)d_in[16];
    const float* W1    = (const float*)d_in[17];
    const float* b1    = (const float*)d_in[18];
    const float* W2    = (const float*)d_in[19];
    const float* b2    = (const float*)d_in[20];
    float* out = (float*)d_out;

    float* buf = nullptr;
    cudaGetSymbolAddress((void**)&buf, g_buf);
    float* Qb    = buf + OFF_Q;
    float* Kb    = buf + OFF_K;
    float* Vb    = buf + OFF_V;
    float* attnb = buf + OFF_ATTN;
    float* res1  = buf + OFF_RES1;
    float* xb    = buf + OFF_X;
    float* ffb   = buf + OFF_FF;
    float* hb    = buf + OFF_H;
    float* comb  = buf + OFF_COMB;

    const dim3 blk(256);
    const dim3 gD(DD / BN, MM / BM);    // N=768
    const dim3 gF(FFD / BN, MM / BM);   // N=3072

    // QKV projections: C = src @ W^T + b
    gemm_k<true,false,false,false><<<gD, blk>>>(src, Wq, bq, nullptr, nullptr, 0, 0, Qb, MM, DD, DD);
    gemm_k<true,false,false,false><<<gD, blk>>>(src, Wk, bk, nullptr, nullptr, 0, 0, Kb, MM, DD, DD);
    gemm_k<true,false,false,false><<<gD, blk>>>(src, Wv, bv, nullptr, nullptr, 0, 0, Vb, MM, DD, DD);

    // attention
    attn_kernel<<<BB * HH * TT, blk>>>(Qb, Kb, Vb, gamma, attnb);

    // out proj + residual(src)
    gemm_k<true,false,false,true><<<gD, blk>>>(attnb, Wo, bo, src, nullptr, 0, 0, res1, MM, DD, DD);

    // LN1 -> x
    ln_kernel<<<MM, blk>>>(res1, nullptr, ln1g, ln1b, xb);

    // gate -> combine weights [M,4]
    gate_kernel<<<MM, 128>>>(xb, Wg, bg, comb);

    // MoE: all 4 experts, combine-weighted accumulate (zero weight = no-op)
    for (int e = 0; e < NE; e++) {
        gemm_k<false,true,false,false><<<gF, blk>>>(
            xb, W1 + (size_t)e * DD * FFD, b1 + (size_t)e * FFD,
            nullptr, nullptr, 0, 0, hb, MM, FFD, DD);
        gemm_k<false,false,true,false><<<gD, blk>>>(
            hb, W2 + (size_t)e * FFD * DD, b2 + (size_t)e * DD,
            nullptr, comb + e, NE, (e == 0) ? 1 : 0, ffb, MM, DD, FFD);
    }

    // LN2 over (x + ff) -> out
    ln_kernel<<<MM, blk>>>(xb, ffb, ln2g, ln2b, out);
}

// round 3
// speedup vs baseline: 1.7687x; 1.7687x over previous
#include <cuda_runtime.h>
#include <cuda_bf16.h>
#include <math.h>

// Problem constants
#define BB 2
#define TT 1024
#define DD 768
#define HH 12
#define HD 64
#define MM (BB*TT)     // 2048
#define FFD 3072
#define NE 4

// ---------------- scratch (static device memory; no runtime alloc) ----------
#define OFF_Q    0
#define OFF_K    (OFF_Q   + MM*DD)
#define OFF_V    (OFF_K   + MM*DD)
#define OFF_ATTN (OFF_V   + MM*DD)
#define OFF_RES1 (OFF_ATTN+ MM*DD)
#define OFF_X    (OFF_RES1+ MM*DD)
#define OFF_FF   (OFF_X   + MM*DD)
#define OFF_H    (OFF_FF  + MM*DD)
#define OFF_COMB (OFF_H   + MM*FFD)
#define BUF_TOTAL (OFF_COMB + MM*NE)

__device__ float g_buf[BUF_TOTAL];
__device__ int   g_cnt[NE];
__device__ int   g_lst[NE * MM];

// ---------------- block reductions (ln/gate) ----------------
__device__ __forceinline__ float blk_reduce_sum(float v, float* red) {
    int tid = threadIdx.x;
    red[tid] = v; __syncthreads();
    for (int s = blockDim.x >> 1; s > 0; s >>= 1) {
        if (tid < s) red[tid] += red[tid + s];
        __syncthreads();
    }
    float r = red[0]; __syncthreads();
    return r;
}

__device__ __forceinline__ float warp_sum(float v) {
    #pragma unroll
    for (int s = 16; s > 0; s >>= 1) v += __shfl_xor_sync(0xffffffffu, v, s);
    return v;
}
__device__ __forceinline__ float warp_max(float v) {
    #pragma unroll
    for (int s = 16; s > 0; s >>= 1) v = fmaxf(v, __shfl_xor_sync(0xffffffffu, v, s));
    return v;
}

// ---------------- generic tiled SGEMM ----------------
// C[M,N] = epi( A[M,K] @ op(B) + bias[N] )
// TRANSB  : B stored [N,K] -> C = A @ B^T  (projection weights)
// RELU    : relu after bias
// AGATHER : A row r comes from gidx list (expert GEMM1); M_eff = *cntp
// SCATW   : C row scattered via gidx, value = comb-weight * v, accumulated (+=)
// RESIDUAL: += resid[m,n]
#define BM 64
#define BN 64
#define BK 16

template<bool TRANSB, bool RELU, bool AGATHER, bool SCATW, bool RESIDUAL>
__global__ __launch_bounds__(256)
void gemm_k(const float* __restrict__ A, const float* __restrict__ B,
            const float* __restrict__ bias,
            const float* __restrict__ resid,
            const int* __restrict__ gidx, const int* __restrict__ cntp,
            const float* __restrict__ rw,
            float* __restrict__ C, int M, int N, int K)
{
    __shared__ float As[BK][BM];
    __shared__ float Bs[BK][BN];
    __shared__ int   idxs[BM];

    const int tid = threadIdx.x;           // 256 threads
    const int bx = blockIdx.x, by = blockIdx.y;
    const int row0 = by * BM, col0 = bx * BN;
    const int tx = tid & 15, ty = tid >> 4;

    int cnt = M;
    if (AGATHER || SCATW) {
        cnt = *cntp;
        if (cnt == 0 || row0 >= cnt) return;
        if (tid < BM) {
            int r = row0 + tid;
            idxs[tid] = gidx[r < cnt ? r : (cnt - 1)];
        }
        __syncthreads();
    }

    // load indices (float4 loads)
    const int lm = tid >> 2;               // 0..63
    const int lk = (tid & 3) * 4;          // 0,4,8,12
    const int bkr = tid >> 4;              // 0..15  (NN path)
    const int bnc = (tid & 15) * 4;        // 0..60  (NN path)

    float acc[4][4] = {};

    for (int k0 = 0; k0 < K; k0 += BK) {
        // A tile
        size_t arow = AGATHER ? (size_t)idxs[lm] : (size_t)(row0 + lm);
        float4 av = *(const float4*)(A + arow * K + k0 + lk);
        As[lk + 0][lm] = av.x; As[lk + 1][lm] = av.y;
        As[lk + 2][lm] = av.z; As[lk + 3][lm] = av.w;
        // B tile
        if (TRANSB) {
            float4 bv = *(const float4*)(B + (size_t)(col0 + lm) * K + k0 + lk);
            Bs[lk + 0][lm] = bv.x; Bs[lk + 1][lm] = bv.y;
            Bs[lk + 2][lm] = bv.z; Bs[lk + 3][lm] = bv.w;
        } else {
            float4 bv = *(const float4*)(B + (size_t)(k0 + bkr) * N + col0 + bnc);
            *(float4*)&Bs[bkr][bnc] = bv;
        }
        __syncthreads();

        #pragma unroll
        for (int kk = 0; kk < BK; kk++) {
            float4 a4 = *(const float4*)&As[kk][ty * 4];
            float4 b4 = *(const float4*)&Bs[kk][tx * 4];
            float a[4] = {a4.x, a4.y, a4.z, a4.w};
            float b[4] = {b4.x, b4.y, b4.z, b4.w};
            #pragma unroll
            for (int i = 0; i < 4; i++)
                #pragma unroll
                for (int j = 0; j < 4; j++)
                    acc[i][j] += a[i] * b[j];
        }
        __syncthreads();
    }

    #pragma unroll
    for (int i = 0; i < 4; i++) {
        const int rl = ty * 4 + i;                 // row within tile
        if ((AGATHER || SCATW) && (row0 + rl >= cnt)) continue;
        #pragma unroll
        for (int j = 0; j < 4; j++) {
            const int c = col0 + tx * 4 + j;
            float v = acc[i][j] + bias[c];
            if (RELU) v = fmaxf(v, 0.0f);
            if (SCATW) {
                int grow = idxs[rl];
                float w = rw[(size_t)grow * NE];
                C[(size_t)grow * N + c] += w * v;
            } else {
                const int r = row0 + rl;
                if (RESIDUAL) v += resid[(size_t)r * N + c];
                C[(size_t)r * N + c] = v;
            }
        }
    }
}

// ---------------- attention v2: block = (b, h, 8-query tile) ----------------
// logits = (Q.K^T)*scale -> gamma * zscore(ddof=1, eps on std) -> softmax -> P@V
// mean-shift cancels in softmax; only sum/sumsq/max/sumexp per row needed.
#define QB 8
#define KC 128

__global__ __launch_bounds__(256)
void attn2_kernel(const float* __restrict__ Qb, const float* __restrict__ Kb,
                  const float* __restrict__ Vb, const float* __restrict__ gamma_p,
                  float* __restrict__ out)
{
    extern __shared__ float sm[];
    float* chunk = sm;                 // KC*64  (K swizzled / V plain)
    float* probs = sm + KC * 64;       // QB*TT
    float* qsm   = probs + QB * TT;    // QB*64

    const int qt = blockIdx.x, h = blockIdx.y, b = blockIdx.z;
    const int tid = threadIdx.x, w = tid >> 5, lane = tid & 31;
    const int q0 = qt * QB;

    // load Q rows for this tile
    if (tid < QB * 16) {
        int qi = tid >> 4, j = tid & 15;
        *(float4*)&qsm[qi * 64 + j * 4] =
            *(const float4*)&Qb[((size_t)(b * TT + q0 + qi)) * DD + h * HD + j * 4];
    }

    const size_t kbase = ((size_t)b * TT) * DD + h * HD;
    float l[32];

    // ---- phase 1: logits (warp w owns query q0+w; lane owns k = c*128+i*32+lane)
    for (int c = 0; c < TT / KC; c++) {
        __syncthreads();
        #pragma unroll
        for (int it = 0; it < (KC * 16) / 256; it++) {
            int idx = tid + it * 256;
            int kr = idx >> 4, j = idx & 15;
            float4 v = *(const float4*)&Kb[kbase + (size_t)(c * KC + kr) * DD + j * 4];
            *(float4*)&chunk[kr * 64 + 4 * (j ^ (kr & 15))] = v;   // XOR swizzle
        }
        __syncthreads();
        #pragma unroll
        for (int i = 0; i < 4; i++) {
            int kr = i * 32 + lane;
            float acc = 0.f;
            #pragma unroll
            for (int j = 0; j < 16; j++) {
                float4 k4 = *(float4*)&chunk[kr * 64 + 4 * (j ^ (kr & 15))];
                float4 q4 = *(float4*)&qsm[w * 64 + j * 4];
                acc += q4.x * k4.x + q4.y * k4.y + q4.z * k4.z + q4.w * k4.w;
            }
            l[c * 4 + i] = acc * 0.125f;   // hd^-0.5
        }
    }

    // ---- per-row stats (warp-level; row == warp's query)
    float s = 0.f, s2 = 0.f;
    #pragma unroll
    for (int r = 0; r < 32; r++) { s += l[r]; s2 += l[r] * l[r]; }
    s = warp_sum(s); s2 = warp_sum(s2);
    float mean = s * (1.0f / TT);
    float var = (s2 - (float)TT * mean * mean) * (1.0f / (TT - 1));
    var = fmaxf(var, 0.0f);
    float denom = sqrtf(var) + 1e-5f;
    float a = (*gamma_p) / denom;

    float mx = -1e30f;
    #pragma unroll
    for (int r = 0; r < 32; r++) { l[r] = a * (l[r] - mean); mx = fmaxf(mx, l[r]); }
    mx = warp_max(mx);
    float es = 0.f;
    #pragma unroll
    for (int r = 0; r < 32; r++) { l[r] = __expf(l[r] - mx); es += l[r]; }
    es = warp_sum(es);
    float rz = 1.0f / es;
    #pragma unroll
    for (int c = 0; c < TT / KC; c++)
        #pragma unroll
        for (int i = 0; i < 4; i++)
            probs[w * TT + c * KC + i * 32 + lane] = l[c * 4 + i] * rz;
    __syncwarp();

    // ---- phase 2: P @ V  (lane owns cols 2*lane, 2*lane+1)
    float o0 = 0.f, o1 = 0.f;
    for (int c = 0; c < TT / KC; c++) {
        __syncthreads();
        #pragma unroll
        for (int it = 0; it < (KC * 16) / 256; it++) {
            int idx = tid + it * 256;
            int kr = idx >> 4, j = idx & 15;
            *(float4*)&chunk[kr * 64 + j * 4] =
                *(const float4*)&Vb[kbase + (size_t)(c * KC + kr) * DD + j * 4];
        }
        __syncthreads();
        const float* pr = &probs[w * TT + c * KC];
        #pragma unroll 8
        for (int k = 0; k < KC; k++) {
            float p = pr[k];
            float2 v = *(float2*)&chunk[k * 64 + lane * 2];
            o0 += p * v.x; o1 += p * v.y;
        }
    }
    float2 o = make_float2(o0, o1);
    *(float2*)&out[((size_t)(b * TT + q0 + w)) * DD + h * HD + lane * 2] = o;
}

// ---------------- layernorm over rows of D=768 ----------------
__global__ __launch_bounds__(256)
void ln_kernel(const float* __restrict__ in, const float* __restrict__ add,
               const float* __restrict__ gw, const float* __restrict__ bw,
               float* __restrict__ out)
{
    const int row = blockIdx.x;
    const int tid = threadIdx.x;  // 256, 3 elems each
    __shared__ float red[256];

    float v[3];
    #pragma unroll
    for (int i = 0; i < 3; i++) {
        int c = tid + i * 256;
        size_t idx = (size_t)row * DD + c;
        v[i] = in[idx] + (add ? add[idx] : 0.0f);
    }
    float tot = blk_reduce_sum(v[0] + v[1] + v[2], red);
    float mean = tot * (1.0f / DD);
    float s2 = 0.f;
    #pragma unroll
    for (int i = 0; i < 3; i++) { float d = v[i] - mean; s2 += d * d; }
    float var = blk_reduce_sum(s2, red) * (1.0f / DD);
    float rstd = rsqrtf(var + 1e-5f);
    #pragma unroll
    for (int i = 0; i < 3; i++) {
        int c = tid + i * 256;
        out[(size_t)row * DD + c] = (v[i] - mean) * rstd * gw[c] + bw[c];
    }
}

// ---------------- zero expert counters ----------------
__global__ void zero_cnt_kernel() {
    if (threadIdx.x < NE) g_cnt[threadIdx.x] = 0;
}

// ---------------- gate: softmax(x@Wg^T+bg) -> top2 combine + expert lists ----
__global__ __launch_bounds__(128)
void gate_kernel(const float* __restrict__ x, const float* __restrict__ Wg,
                 const float* __restrict__ bg, float* __restrict__ comb)
{
    const int row = blockIdx.x;
    const int tid = threadIdx.x; // 128
    float acc[NE] = {};
    for (int d = tid; d < DD; d += 128) {
        float xv = x[(size_t)row * DD + d];
        #pragma unroll
        for (int e = 0; e < NE; e++) acc[e] += xv * Wg[e * DD + d];
    }
    __shared__ float red[NE][128];
    #pragma unroll
    for (int e = 0; e < NE; e++) red[e][tid] = acc[e];
    __syncthreads();
    for (int s = 64; s > 0; s >>= 1) {
        if (tid < s) {
            #pragma unroll
            for (int e = 0; e < NE; e++) red[e][tid] += red[e][tid + s];
        }
        __syncthreads();
    }
    if (tid == 0) {
        float sc[NE];
        #pragma unroll
        for (int e = 0; e < NE; e++) sc[e] = red[e][0] + bg[e];
        float m = sc[0];
        #pragma unroll
        for (int e = 1; e < NE; e++) m = fmaxf(m, sc[e]);
        float p[NE], Z = 0.f;
        #pragma unroll
        for (int e = 0; e < NE; e++) { p[e] = __expf(sc[e] - m); Z += p[e]; }
        #pragma unroll
        for (int e = 0; e < NE; e++) p[e] /= Z;
        // top-2, first-index tie-break (strict >)
        int i1 = 0;
        for (int e = 1; e < NE; e++) if (p[e] > p[i1]) i1 = e;
        int i2 = -1;
        for (int e = 0; e < NE; e++) {
            if (e == i1) continue;
            if (i2 < 0 || p[e] > p[i2]) i2 = e;
        }
        #pragma unroll
        for (int e = 0; e < NE; e++)
            comb[(size_t)row * NE + e] = (e == i1 || e == i2) ? p[e] : 0.0f;
        int p1 = atomicAdd(&g_cnt[i1], 1);
        g_lst[i1 * MM + p1] = row;
        int p2 = atomicAdd(&g_cnt[i2], 1);
        g_lst[i2 * MM + p2] = row;
    }
}

// ---------------- launcher ----------------
extern "C" void kernel_launch(void* const* d_in, const int* in_sizes, int n_in,
                              void* d_out, int out_size)
{
    (void)in_sizes; (void)n_in; (void)out_size;
    const float* src   = (const float*)d_in[0];
    // d_in[1] = frac (unused in this reference path)
    const float* Wq    = (const float*)d_in[2];
    const float* bq    = (const float*)d_in[3];
    const float* Wk    = (const float*)d_in[4];
    const float* bk    = (const float*)d_in[5];
    const float* Wv    = (const float*)d_in[6];
    const float* bv    = (const float*)d_in[7];
    const float* Wo    = (const float*)d_in[8];
    const float* bo    = (const float*)d_in[9];
    const float* gamma = (const float*)d_in[10];
    const float* ln1g  = (const float*)d_in[11];
    const float* ln1b  = (const float*)d_in[12];
    const float* ln2g  = (const float*)d_in[13];
    const float* ln2b  = (const float*)d_in[14];
    const float* Wg    = (const float*)d_in[15];
    const float* bg    = (const float*)d_in[16];
    const float* W1    = (const float*)d_in[17];
    const float* b1    = (const float*)d_in[18];
    const float* W2    = (const float*)d_in[19];
    const float* b2    = (const float*)d_in[20];
    float* out = (float*)d_out;

    float* buf = nullptr;
    cudaGetSymbolAddress((void**)&buf, g_buf);
    int* cntp = nullptr;
    cudaGetSymbolAddress((void**)&cntp, g_cnt);
    int* lstp = nullptr;
    cudaGetSymbolAddress((void**)&lstp, g_lst);

    float* Qb    = buf + OFF_Q;
    float* Kb    = buf + OFF_K;
    float* Vb    = buf + OFF_V;
    float* attnb = buf + OFF_ATTN;
    float* res1  = buf + OFF_RES1;
    float* xb    = buf + OFF_X;
    float* ffb   = buf + OFF_FF;
    float* hb    = buf + OFF_H;
    float* comb  = buf + OFF_COMB;

    const dim3 blk(256);
    const dim3 gD(DD / BN, MM / BM);    // N=768
    const dim3 gF(FFD / BN, MM / BM);   // N=3072

    static bool attn_attr_set = false;
    const int attn_smem = (KC * 64 + QB * TT + QB * 64) * sizeof(float);
    if (!attn_attr_set) {
        cudaFuncSetAttribute(attn2_kernel, cudaFuncAttributeMaxDynamicSharedMemorySize, attn_smem);
        attn_attr_set = true;
    }

    zero_cnt_kernel<<<1, 32>>>();

    // QKV projections: C = src @ W^T + b
    gemm_k<true,false,false,false,false><<<gD, blk>>>(src, Wq, bq, nullptr, nullptr, nullptr, nullptr, Qb, MM, DD, DD);
    gemm_k<true,false,false,false,false><<<gD, blk>>>(src, Wk, bk, nullptr, nullptr, nullptr, nullptr, Kb, MM, DD, DD);
    gemm_k<true,false,false,false,false><<<gD, blk>>>(src, Wv, bv, nullptr, nullptr, nullptr, nullptr, Vb, MM, DD, DD);

    // attention
    attn2_kernel<<<dim3(TT / QB, HH, BB), blk, attn_smem>>>(Qb, Kb, Vb, gamma, attnb);

    // out proj + residual(src)
    gemm_k<true,false,false,false,true><<<gD, blk>>>(attnb, Wo, bo, src, nullptr, nullptr, nullptr, res1, MM, DD, DD);

    // LN1 -> x
    ln_kernel<<<MM, blk>>>(res1, nullptr, ln1g, ln1b, xb);

    // gate -> combine weights [M,4] + per-expert row lists
    gate_kernel<<<MM, 128>>>(xb, Wg, bg, comb);

    // ff accumulator zero
    cudaMemsetAsync(ffb, 0, (size_t)MM * DD * sizeof(float));

    // MoE: top-2 sparse — per expert, gathered GEMM1 (relu) then scatter GEMM2
    for (int e = 0; e < NE; e++) {
        gemm_k<false,true,true,false,false><<<gF, blk>>>(
            xb, W1 + (size_t)e * DD * FFD, b1 + (size_t)e * FFD,
            nullptr, lstp + e * MM, cntp + e, nullptr, hb, MM, FFD, DD);
        gemm_k<false,false,false,true,false><<<gD, blk>>>(
            hb, W2 + (size_t)e * FFD * DD, b2 + (size_t)e * DD,
            nullptr, lstp + e * MM, cntp + e, comb + e, ffb, MM, DD, FFD);
    }

    // LN2 over (x + ff) -> out
    ln_kernel<<<MM, blk>>>(xb, ffb, ln2g, ln2b, out);
}

// round 12
// speedup vs baseline: 2.9440x; 1.6645x over previous
#include <cuda_runtime.h>
#include <cuda_bf16.h>
#include <math.h>

// Problem constants
#define BB 2
#define TT 1024
#define DD 768
#define HH 12
#define HD 64
#define MM (BB*TT)     // 2048
#define FFD 3072
#define NE 4

typedef __nv_bfloat16 bf16;

// ================= static scratch (no runtime alloc) =================
#define OFF_Q    0
#define OFF_K    (OFF_Q   + MM*DD)
#define OFF_V    (OFF_K   + MM*DD)
#define OFF_RES1 (OFF_V   + MM*DD)
#define OFF_X    (OFF_RES1+ MM*DD)
#define OFF_FF   (OFF_X   + MM*DD)
#define OFF_COMB (OFF_FF  + MM*DD)
#define F32_TOTAL (OFF_COMB + MM*NE)
__device__ __align__(256) float g_f32[F32_TOTAL];

#define BO_SRCH 0
#define BO_SRCL (BO_SRCH + MM*DD)
#define BO_AH   (BO_SRCL + MM*DD)
#define BO_AL   (BO_AH   + MM*DD)
#define BO_XH   (BO_AL   + MM*DD)
#define BO_XL   (BO_XH   + MM*DD)
#define BO_HH   (BO_XL   + MM*DD)
#define BO_HL   (BO_HH   + MM*FFD)
#define BO_WQH  (BO_HL   + MM*FFD)
#define BO_WQL  (BO_WQH  + DD*DD)
#define BO_WKH  (BO_WQL  + DD*DD)
#define BO_WKL  (BO_WKH  + DD*DD)
#define BO_WVH  (BO_WKL  + DD*DD)
#define BO_WVL  (BO_WVH  + DD*DD)
#define BO_WOH  (BO_WVL  + DD*DD)
#define BO_WOL  (BO_WOH  + DD*DD)
#define BO_W1TH (BO_WOL  + DD*DD)
#define BO_W1TL (BO_W1TH + NE*DD*FFD)
#define BO_W2TH (BO_W1TL + NE*DD*FFD)
#define BO_W2TL (BO_W2TH + NE*DD*FFD)
#define BF_TOTAL (BO_W2TL + NE*DD*FFD)
__device__ __align__(256) bf16 g_bf[BF_TOTAL];

__device__ int g_cnt[NE];
__device__ int g_lst[NE * MM];

// ================= PTX helpers =================
__device__ __forceinline__ unsigned smem_u32(const void* p) {
    unsigned a;
    asm("{ .reg .u64 t; cvta.to.shared.u64 t, %1; cvt.u32.u64 %0, t; }" : "=r"(a) : "l"(p));
    return a;
}

#define CP_ASYNC16(sm, gp) \
    asm volatile("cp.async.cg.shared.global [%0], [%1], 16;" :: "r"(sm), "l"(gp))
#define CP_COMMIT() asm volatile("cp.async.commit_group;" ::: "memory")
#define CP_WAIT(n)  asm volatile("cp.async.wait_group %0;" :: "n"(n) : "memory")

#define LDMATRIX_X4(r0, r1, r2, r3, addr) \
    asm volatile("ldmatrix.sync.aligned.m8n8.x4.shared.b16 {%0,%1,%2,%3}, [%4];" \
        : "=r"(r0), "=r"(r1), "=r"(r2), "=r"(r3) : "r"(addr))

#define MMA_BF16(d, a, b0, b1) \
    asm volatile("mma.sync.aligned.m16n8k16.row.col.f32.bf16.bf16.f32 " \
        "{%0,%1,%2,%3}, {%4,%5,%6,%7}, {%8,%9}, {%0,%1,%2,%3};" \
        : "+f"((d)[0]), "+f"((d)[1]), "+f"((d)[2]), "+f"((d)[3]) \
        : "r"((a)[0]), "r"((a)[1]), "r"((a)[2]), "r"((a)[3]), "r"(b0), "r"(b1))

__device__ __forceinline__ void split2(float x, bf16& h, bf16& l) {
    h = __float2bfloat16_rn(x);
    l = __float2bfloat16_rn(x - __bfloat162float(h));
}

// ================= reductions =================
__device__ __forceinline__ float blk_reduce_sum(float v, float* red) {
    int tid = threadIdx.x;
    red[tid] = v; __syncthreads();
    for (int s = blockDim.x >> 1; s > 0; s >>= 1) {
        if (tid < s) red[tid] += red[tid + s];
        __syncthreads();
    }
    float r = red[0]; __syncthreads();
    return r;
}
__device__ __forceinline__ float warp_sum(float v) {
    #pragma unroll
    for (int s = 16; s > 0; s >>= 1) v += __shfl_xor_sync(0xffffffffu, v, s);
    return v;
}
__device__ __forceinline__ float warp_max(float v) {
    #pragma unroll
    for (int s = 16; s > 0; s >>= 1) v = fmaxf(v, __shfl_xor_sync(0xffffffffu, v, s));
    return v;
}

// ================= split-bf16 GEMM via mma.sync (HMMA) =================
// C[M,N] = epi( A @ B^T ), A = Ah+Al, B = Bh+Bl (bf16 hi/lo, K-major rows)
// 3 products: (Ah,Bh), (Ah,Bl), (Al,Bh) accumulated in fp32.
// MODE 0: Cf = acc + bias                  (QKV)
// MODE 1: Cf = acc + bias + resid          (O-proj)
// MODE 2: relu(acc+bias) -> split bf16 Chh/Chl, compacted rows (MoE up)
// MODE 3: Cf[gidx[r]] += rw[gidx[r]*NE]*(acc+bias)             (MoE down)
#define BM 128
#define BN 128
#define BKC 64
#define NSTAGE 3
#define STAGEB (2 * BM * BKC * 2)           // A tile + B tile = 32768 B
#define GSMEM_BYTES (1024 + 1024 + NSTAGE * STAGEB)

template<int MODE, bool GATHERA>
__global__ __launch_bounds__(256)
void gemm_mma(const bf16* __restrict__ Ah, const bf16* __restrict__ Al,
              const bf16* __restrict__ Bh, const bf16* __restrict__ Bl,
              const float* __restrict__ bias, const float* __restrict__ resid,
              const int* __restrict__ gidx, const int* __restrict__ cntp,
              const float* __restrict__ rw,
              float* __restrict__ Cf, bf16* __restrict__ Chh, bf16* __restrict__ Chl,
              int Mtot, int Ng, int K)
{
    const int tid = threadIdx.x;
    const int lane = tid & 31;
    const int wid = tid >> 5;
    const int wrow = (wid & 1) * 64;   // warp tile row offset (2 x 64)
    const int wcol = (wid >> 1) * 32;  // warp tile col offset (4 x 32)
    const int col0 = blockIdx.x * BN;
    const int row0 = blockIdx.y * BM;

    int cnt = Mtot;
    if (MODE == 2 || MODE == 3 || GATHERA) {
        cnt = *cntp;
        if (cnt == 0 || row0 >= cnt) return;
    }

    extern __shared__ char rawsm[];
    unsigned rawb = smem_u32(rawsm);
    unsigned base = (rawb + 1023u) & ~1023u;
    char* smp = rawsm + (base - rawb);
    int* idxs = (int*)smp;                 // [0:512) row indices
    unsigned stg = base + 1024;            // pipeline stages
    float* stag = (float*)(smp + 1024);    // epilogue staging (reuses stages)

    if ((GATHERA || MODE == 3) && tid < BM) {
        int r = row0 + tid;
        idxs[tid] = gidx[r < cnt ? r : (cnt - 1)];
    }
    __syncthreads();

    const int nck = K / BKC;
    const int NC = 3 * nck;

    float d[4][4][4];
    #pragma unroll
    for (int mf = 0; mf < 4; mf++)
        #pragma unroll
        for (int nf = 0; nf < 4; nf++)
            #pragma unroll
            for (int i = 0; i < 4; i++) d[mf][nf][i] = 0.f;

    // ---- async loader for chunk c (product p, k-offset kc*64)
    auto issue = [&](int c) {
        int p = c / nck, kc = c - p * nck, k0 = kc * BKC;
        const bf16* Asrc = (p == 2) ? Al : Ah;
        const bf16* Bsrc = (p == 1) ? Bl : Bh;
        unsigned sb = stg + (c % NSTAGE) * STAGEB;
        #pragma unroll
        for (int it = 0; it < 4; it++) {
            int u = tid + it * 256;
            int row = u >> 3, seg = u & 7;
            int ar = GATHERA ? idxs[row] : (row0 + row);
            const bf16* gp = Asrc + (size_t)ar * K + k0 + seg * 8;
            unsigned off = row * 128 + seg * 16;
            off ^= (off >> 3) & 0x70;
            CP_ASYNC16(sb + off, gp);
        }
        #pragma unroll
        for (int it = 0; it < 4; it++) {
            int u = tid + it * 256;
            int row = u >> 3, seg = u & 7;
            const bf16* gp = Bsrc + (size_t)(col0 + row) * K + k0 + seg * 8;
            unsigned off = row * 128 + seg * 16;
            off ^= (off >> 3) & 0x70;
            CP_ASYNC16(sb + 16384 + off, gp);
        }
    };

    for (int s = 0; s < NSTAGE - 1; s++) { issue(s); CP_COMMIT(); }

    for (int c = 0; c < NC; c++) {
        CP_WAIT(NSTAGE - 2);
        __syncthreads();
        if (c + NSTAGE - 1 < NC) issue(c + NSTAGE - 1);
        CP_COMMIT();   // unconditional: keeps wait_group counting exact at tail

        unsigned Ab = stg + (c % NSTAGE) * STAGEB;
        unsigned Bb = Ab + 16384;
        #pragma unroll
        for (int ks = 0; ks < 4; ks++) {
            const int kb = ks * 32;  // bytes
            unsigned a[4][4];
            #pragma unroll
            for (int mf = 0; mf < 4; mf++) {
                int row = wrow + mf * 16 + ((lane >> 3) & 1) * 8 + (lane & 7);
                int cb = kb + (lane >> 4) * 16;
                unsigned ad = Ab + row * 128 + (cb ^ ((row & 7) << 4));
                LDMATRIX_X4(a[mf][0], a[mf][1], a[mf][2], a[mf][3], ad);
            }
            unsigned bq[2][4];
            #pragma unroll
            for (int g = 0; g < 2; g++) {
                int row = wcol + g * 16 + (lane >> 4) * 8 + (lane & 7);
                int cb = kb + ((lane >> 3) & 1) * 16;
                unsigned ad = Bb + row * 128 + (cb ^ ((row & 7) << 4));
                LDMATRIX_X4(bq[g][0], bq[g][1], bq[g][2], bq[g][3], ad);
            }
            #pragma unroll
            for (int mf = 0; mf < 4; mf++)
                #pragma unroll
                for (int nf = 0; nf < 4; nf++)
                    MMA_BF16(d[mf][nf], a[mf], bq[nf >> 1][(nf & 1) * 2],
                             bq[nf >> 1][(nf & 1) * 2 + 1]);
        }
    }
    __syncthreads();   // all compute done; safe to reuse stage smem as staging

    // ---- accum -> smem staging (stride 132 keeps float2 aligned)
    #pragma unroll
    for (int mf = 0; mf < 4; mf++)
        #pragma unroll
        for (int nf = 0; nf < 4; nf++) {
            int r = wrow + mf * 16 + (lane >> 2);
            int cc = wcol + nf * 8 + (lane & 3) * 2;
            *(float2*)&stag[r * 132 + cc] = make_float2(d[mf][nf][0], d[mf][nf][1]);
            *(float2*)&stag[(r + 8) * 132 + cc] = make_float2(d[mf][nf][2], d[mf][nf][3]);
        }
    __syncthreads();

    // ---- staging -> global (coalesced float4)
    #pragma unroll 4
    for (int i = 0; i < 16; i++) {
        int flat = i * 256 + tid;
        int row = flat >> 5;
        int seg = flat & 31;
        if ((MODE == 2 || MODE == 3) && (row0 + row >= cnt)) continue;
        int gc = col0 + seg * 4;
        float4 bi = *(const float4*)&bias[gc];
        float v0 = stag[row * 132 + seg * 4 + 0] + bi.x;
        float v1 = stag[row * 132 + seg * 4 + 1] + bi.y;
        float v2 = stag[row * 132 + seg * 4 + 2] + bi.z;
        float v3 = stag[row * 132 + seg * 4 + 3] + bi.w;

        if (MODE == 0 || MODE == 1) {
            size_t idx = (size_t)(row0 + row) * Ng + gc;
            if (MODE == 1) {
                float4 rs = *(const float4*)&resid[idx];
                v0 += rs.x; v1 += rs.y; v2 += rs.z; v3 += rs.w;
            }
            *(float4*)&Cf[idx] = make_float4(v0, v1, v2, v3);
        } else if (MODE == 2) {
            v0 = fmaxf(v0, 0.f); v1 = fmaxf(v1, 0.f);
            v2 = fmaxf(v2, 0.f); v3 = fmaxf(v3, 0.f);
            bf16 h4[4] __align__(8), l4[4] __align__(8);
            split2(v0, h4[0], l4[0]); split2(v1, h4[1], l4[1]);
            split2(v2, h4[2], l4[2]); split2(v3, h4[3], l4[3]);
            size_t idx = (size_t)(row0 + row) * Ng + gc;
            *(uint2*)&Chh[idx] = *(uint2*)h4;
            *(uint2*)&Chl[idx] = *(uint2*)l4;
        } else { // MODE 3
            int grow = idxs[row];
            float w = rw[(size_t)grow * NE];
            size_t idx = (size_t)grow * Ng + gc;
            float4 p = *(float4*)&Cf[idx];
            p.x += w * v0; p.y += w * v1; p.z += w * v2; p.w += w * v3;
            *(float4*)&Cf[idx] = p;
        }
    }
}

// ================= attention (emits bf16 hi/lo) =================
#define QB 8
#define KC 128

__global__ __launch_bounds__(256)
void attn2_kernel(const float* __restrict__ Qb, const float* __restrict__ Kb,
                  const float* __restrict__ Vb, const float* __restrict__ gamma_p,
                  bf16* __restrict__ oh, bf16* __restrict__ ol)
{
    extern __shared__ float sm[];
    float* chunk = sm;                 // KC*64
    float* probs = sm + KC * 64;       // QB*TT
    float* qsm   = probs + QB * TT;    // QB*64

    const int qt = blockIdx.x, h = blockIdx.y, b = blockIdx.z;
    const int tid = threadIdx.x, w = tid >> 5, lane = tid & 31;
    const int q0 = qt * QB;

    if (tid < QB * 16) {
        int qi = tid >> 4, j = tid & 15;
        *(float4*)&qsm[qi * 64 + j * 4] =
            *(const float4*)&Qb[((size_t)(b * TT + q0 + qi)) * DD + h * HD + j * 4];
    }

    const size_t kbase = ((size_t)b * TT) * DD + h * HD;
    float l[32];

    for (int c = 0; c < TT / KC; c++) {
        __syncthreads();
        #pragma unroll
        for (int it = 0; it < (KC * 16) / 256; it++) {
            int idx = tid + it * 256;
            int kr = idx >> 4, j = idx & 15;
            float4 v = *(const float4*)&Kb[kbase + (size_t)(c * KC + kr) * DD + j * 4];
            *(float4*)&chunk[kr * 64 + 4 * (j ^ (kr & 15))] = v;
        }
        __syncthreads();
        #pragma unroll
        for (int i = 0; i < 4; i++) {
            int kr = i * 32 + lane;
            float acc = 0.f;
            #pragma unroll
            for (int j = 0; j < 16; j++) {
                float4 k4 = *(float4*)&chunk[kr * 64 + 4 * (j ^ (kr & 15))];
                float4 q4 = *(float4*)&qsm[w * 64 + j * 4];
                acc += q4.x * k4.x + q4.y * k4.y + q4.z * k4.z + q4.w * k4.w;
            }
            l[c * 4 + i] = acc * 0.125f;
        }
    }

    float s = 0.f, s2 = 0.f;
    #pragma unroll
    for (int r = 0; r < 32; r++) { s += l[r]; s2 += l[r] * l[r]; }
    s = warp_sum(s); s2 = warp_sum(s2);
    float mean = s * (1.0f / TT);
    float var = (s2 - (float)TT * mean * mean) * (1.0f / (TT - 1));
    var = fmaxf(var, 0.0f);
    float denom = sqrtf(var) + 1e-5f;
    float a = (*gamma_p) / denom;

    float mx = -1e30f;
    #pragma unroll
    for (int r = 0; r < 32; r++) { l[r] = a * (l[r] - mean); mx = fmaxf(mx, l[r]); }
    mx = warp_max(mx);
    float es = 0.f;
    #pragma unroll
    for (int r = 0; r < 32; r++) { l[r] = __expf(l[r] - mx); es += l[r]; }
    es = warp_sum(es);
    float rz = 1.0f / es;
    #pragma unroll
    for (int c = 0; c < TT / KC; c++)
        #pragma unroll
        for (int i = 0; i < 4; i++)
            probs[w * TT + c * KC + i * 32 + lane] = l[c * 4 + i] * rz;
    __syncwarp();

    float o0 = 0.f, o1 = 0.f;
    for (int c = 0; c < TT / KC; c++) {
        __syncthreads();
        #pragma unroll
        for (int it = 0; it < (KC * 16) / 256; it++) {
            int idx = tid + it * 256;
            int kr = idx >> 4, j = idx & 15;
            *(float4*)&chunk[kr * 64 + j * 4] =
                *(const float4*)&Vb[kbase + (size_t)(c * KC + kr) * DD + j * 4];
        }
        __syncthreads();
        const float* pr = &probs[w * TT + c * KC];
        #pragma unroll 8
        for (int k = 0; k < KC; k++) {
            float p = pr[k];
            float2 v = *(float2*)&chunk[k * 64 + lane * 2];
            o0 += p * v.x; o1 += p * v.y;
        }
    }
    bf16 h0, l0, h1, l1;
    split2(o0, h0, l0); split2(o1, h1, l1);
    size_t oidx = ((size_t)(b * TT + q0 + w)) * DD + h * HD + lane * 2;
    __nv_bfloat162 hv; hv.x = h0; hv.y = h1;
    __nv_bfloat162 lv; lv.x = l0; lv.y = l1;
    *(__nv_bfloat162*)&oh[oidx] = hv;
    *(__nv_bfloat162*)&ol[oidx] = lv;
}

// ================= layernorm (optional bf16 hi/lo emit) =================
__global__ __launch_bounds__(256)
void ln_kernel(const float* __restrict__ in, const float* __restrict__ add,
               const float* __restrict__ gw, const float* __restrict__ bw,
               float* __restrict__ out, bf16* __restrict__ oh, bf16* __restrict__ ol)
{
    const int row = blockIdx.x;
    const int tid = threadIdx.x;
    __shared__ float red[256];

    float v[3];
    #pragma unroll
    for (int i = 0; i < 3; i++) {
        int c = tid + i * 256;
        size_t idx = (size_t)row * DD + c;
        v[i] = in[idx] + (add ? add[idx] : 0.0f);
    }
    float tot = blk_reduce_sum(v[0] + v[1] + v[2], red);
    float mean = tot * (1.0f / DD);
    float s2 = 0.f;
    #pragma unroll
    for (int i = 0; i < 3; i++) { float dd = v[i] - mean; s2 += dd * dd; }
    float var = blk_reduce_sum(s2, red) * (1.0f / DD);
    float rstd = rsqrtf(var + 1e-5f);
    #pragma unroll
    for (int i = 0; i < 3; i++) {
        int c = tid + i * 256;
        size_t idx = (size_t)row * DD + c;
        float y = (v[i] - mean) * rstd * gw[c] + bw[c];
        out[idx] = y;
        if (oh) { bf16 hh, ll; split2(y, hh, ll); oh[idx] = hh; ol[idx] = ll; }
    }
}

// ================= conversions =================
__global__ __launch_bounds__(256)
void split_kernel(const float* __restrict__ in, bf16* __restrict__ oh,
                  bf16* __restrict__ ol, int n4)
{
    int i = blockIdx.x * 256 + threadIdx.x;
    if (i >= n4) return;
    float4 v = *(const float4*)&in[i * 4];
    bf16 h4[4] __align__(8), l4[4] __align__(8);
    split2(v.x, h4[0], l4[0]); split2(v.y, h4[1], l4[1]);
    split2(v.z, h4[2], l4[2]); split2(v.w, h4[3], l4[3]);
    *(uint2*)&oh[i * 4] = *(uint2*)h4;
    *(uint2*)&ol[i * 4] = *(uint2*)l4;
}

__global__ __launch_bounds__(256)
void tsplit_kernel(const float* __restrict__ in, bf16* __restrict__ oh,
                   bf16* __restrict__ ol, int Kd, int Nd)
{
    __shared__ float t[32][33];
    int e = blockIdx.z;
    const float* ip = in + (size_t)e * Kd * Nd;
    bf16* hp = oh + (size_t)e * Kd * Nd;
    bf16* lp = ol + (size_t)e * Kd * Nd;
    int n0 = blockIdx.x * 32, k0 = blockIdx.y * 32;
    int tx = threadIdx.x, ty = threadIdx.y;  // 32 x 8
    #pragma unroll
    for (int r = 0; r < 4; r++)
        t[ty + 8 * r][tx] = ip[(size_t)(k0 + ty + 8 * r) * Nd + n0 + tx];
    __syncthreads();
    #pragma unroll
    for (int r = 0; r < 4; r++) {
        float v = t[tx][ty + 8 * r];
        bf16 hh, ll; split2(v, hh, ll);
        size_t idx = (size_t)(n0 + ty + 8 * r) * Kd + k0 + tx;
        hp[idx] = hh; lp[idx] = ll;
    }
}

// ================= counters / gate =================
__global__ void zero_cnt_kernel() {
    if (threadIdx.x < NE) g_cnt[threadIdx.x] = 0;
}

__global__ __launch_bounds__(128)
void gate_kernel(const float* __restrict__ x, const float* __restrict__ Wg,
                 const float* __restrict__ bg, float* __restrict__ comb)
{
    const int row = blockIdx.x;
    const int tid = threadIdx.x;
    float acc[NE] = {};
    for (int d = tid; d < DD; d += 128) {
        float xv = x[(size_t)row * DD + d];
        #pragma unroll
        for (int e = 0; e < NE; e++) acc[e] += xv * Wg[e * DD + d];
    }
    __shared__ float red[NE][128];
    #pragma unroll
    for (int e = 0; e < NE; e++) red[e][tid] = acc[e];
    __syncthreads();
    for (int s = 64; s > 0; s >>= 1) {
        if (tid < s) {
            #pragma unroll
            for (int e = 0; e < NE; e++) red[e][tid] += red[e][tid + s];
        }
        __syncthreads();
    }
    if (tid == 0) {
        float sc[NE];
        #pragma unroll
        for (int e = 0; e < NE; e++) sc[e] = red[e][0] + bg[e];
        float m = sc[0];
        #pragma unroll
        for (int e = 1; e < NE; e++) m = fmaxf(m, sc[e]);
        float p[NE], Z = 0.f;
        #pragma unroll
        for (int e = 0; e < NE; e++) { p[e] = __expf(sc[e] - m); Z += p[e]; }
        #pragma unroll
        for (int e = 0; e < NE; e++) p[e] /= Z;
        int i1 = 0;
        for (int e = 1; e < NE; e++) if (p[e] > p[i1]) i1 = e;
        int i2 = -1;
        for (int e = 0; e < NE; e++) {
            if (e == i1) continue;
            if (i2 < 0 || p[e] > p[i2]) i2 = e;
        }
        #pragma unroll
        for (int e = 0; e < NE; e++)
            comb[(size_t)row * NE + e] = (e == i1 || e == i2) ? p[e] : 0.0f;
        int p1 = atomicAdd(&g_cnt[i1], 1);
        g_lst[i1 * MM + p1] = row;
        int p2 = atomicAdd(&g_cnt[i2], 1);
        g_lst[i2 * MM + p2] = row;
    }
}

// ================= launcher =================
extern "C" void kernel_launch(void* const* d_in, const int* in_sizes, int n_in,
                              void* d_out, int out_size)
{
    (void)in_sizes; (void)n_in; (void)out_size;
    const float* src   = (const float*)d_in[0];
    const float* Wq    = (const float*)d_in[2];
    const float* bq    = (const float*)d_in[3];
    const float* Wk    = (const float*)d_in[4];
    const float* bk    = (const float*)d_in[5];
    const float* Wv    = (const float*)d_in[6];
    const float* bv    = (const float*)d_in[7];
    const float* Wo    = (const float*)d_in[8];
    const float* bo    = (const float*)d_in[9];
    const float* gamma = (const float*)d_in[10];
    const float* ln1g  = (const float*)d_in[11];
    const float* ln1b  = (const float*)d_in[12];
    const float* ln2g  = (const float*)d_in[13];
    const float* ln2b  = (const float*)d_in[14];
    const float* Wg    = (const float*)d_in[15];
    const float* bg    = (const float*)d_in[16];
    const float* W1    = (const float*)d_in[17];
    const float* b1    = (const float*)d_in[18];
    const float* W2    = (const float*)d_in[19];
    const float* b2    = (const float*)d_in[20];
    float* out = (float*)d_out;

    float* fb = nullptr; cudaGetSymbolAddress((void**)&fb, g_f32);
    bf16*  bb = nullptr; cudaGetSymbolAddress((void**)&bb, g_bf);
    int* cntp = nullptr; cudaGetSymbolAddress((void**)&cntp, g_cnt);
    int* lstp = nullptr; cudaGetSymbolAddress((void**)&lstp, g_lst);

    float* Qb   = fb + OFF_Q;
    float* Kb   = fb + OFF_K;
    float* Vb   = fb + OFF_V;
    float* res1 = fb + OFF_RES1;
    float* xb   = fb + OFF_X;
    float* ffb  = fb + OFF_FF;
    float* comb = fb + OFF_COMB;

    bf16 *srch = bb + BO_SRCH, *srcl = bb + BO_SRCL;
    bf16 *ah   = bb + BO_AH,   *al   = bb + BO_AL;
    bf16 *xh   = bb + BO_XH,   *xl   = bb + BO_XL;
    bf16 *hh   = bb + BO_HH,   *hl   = bb + BO_HL;
    bf16 *wqh  = bb + BO_WQH,  *wql  = bb + BO_WQL;
    bf16 *wkh  = bb + BO_WKH,  *wkl  = bb + BO_WKL;
    bf16 *wvh  = bb + BO_WVH,  *wvl  = bb + BO_WVL;
    bf16 *woh  = bb + BO_WOH,  *wol  = bb + BO_WOL;
    bf16 *w1th = bb + BO_W1TH, *w1tl = bb + BO_W1TL;
    bf16 *w2th = bb + BO_W2TH, *w2tl = bb + BO_W2TL;

    static bool attrs_set = false;
    const int attn_smem = (KC * 64 + QB * TT + QB * 64) * sizeof(float);
    if (!attrs_set) {
        cudaFuncSetAttribute(attn2_kernel, cudaFuncAttributeMaxDynamicSharedMemorySize, attn_smem);
        cudaFuncSetAttribute(gemm_mma<0, false>, cudaFuncAttributeMaxDynamicSharedMemorySize, GSMEM_BYTES);
        cudaFuncSetAttribute(gemm_mma<1, false>, cudaFuncAttributeMaxDynamicSharedMemorySize, GSMEM_BYTES);
        cudaFuncSetAttribute(gemm_mma<2, true >, cudaFuncAttributeMaxDynamicSharedMemorySize, GSMEM_BYTES);
        cudaFuncSetAttribute(gemm_mma<3, false>, cudaFuncAttributeMaxDynamicSharedMemorySize, GSMEM_BYTES);
        attrs_set = true;
    }

    // ---- conversions
    split_kernel<<<(MM * DD / 4 + 255) / 256, 256>>>(src, srch, srcl, MM * DD / 4);
    split_kernel<<<(DD * DD / 4 + 255) / 256, 256>>>(Wq, wqh, wql, DD * DD / 4);
    split_kernel<<<(DD * DD / 4 + 255) / 256, 256>>>(Wk, wkh, wkl, DD * DD / 4);
    split_kernel<<<(DD * DD / 4 + 255) / 256, 256>>>(Wv, wvh, wvl, DD * DD / 4);
    split_kernel<<<(DD * DD / 4 + 255) / 256, 256>>>(Wo, woh, wol, DD * DD / 4);
    tsplit_kernel<<<dim3(FFD / 32, DD / 32, NE), dim3(32, 8)>>>(W1, w1th, w1tl, DD, FFD);
    tsplit_kernel<<<dim3(DD / 32, FFD / 32, NE), dim3(32, 8)>>>(W2, w2th, w2tl, FFD, DD);

    zero_cnt_kernel<<<1, 32>>>();

    // ---- QKV projections (HMMA)
    const dim3 gblk(256);
    const dim3 gD(DD / BN, MM / BM);   // (6,16)
    const dim3 gF(FFD / BN, MM / BM);  // (24,16)
    gemm_mma<0, false><<<gD, gblk, GSMEM_BYTES>>>(srch, srcl, wqh, wql, bq,
        nullptr, nullptr, nullptr, nullptr, Qb, nullptr, nullptr, MM, DD, DD);
    gemm_mma<0, false><<<gD, gblk, GSMEM_BYTES>>>(srch, srcl, wkh, wkl, bk,
        nullptr, nullptr, nullptr, nullptr, Kb, nullptr, nullptr, MM, DD, DD);
    gemm_mma<0, false><<<gD, gblk, GSMEM_BYTES>>>(srch, srcl, wvh, wvl, bv,
        nullptr, nullptr, nullptr, nullptr, Vb, nullptr, nullptr, MM, DD, DD);

    // ---- attention (emits bf16 hi/lo)
    attn2_kernel<<<dim3(TT / QB, HH, BB), 256, attn_smem>>>(Qb, Kb, Vb, gamma, ah, al);

    // ---- out-proj + residual
    gemm_mma<1, false><<<gD, gblk, GSMEM_BYTES>>>(ah, al, woh, wol, bo,
        src, nullptr, nullptr, nullptr, res1, nullptr, nullptr, MM, DD, DD);

    // ---- LN1 (emits x fp32 + bf16 hi/lo)
    ln_kernel<<<MM, 256>>>(res1, nullptr, ln1g, ln1b, xb, xh, xl);

    // ---- gate
    gate_kernel<<<MM, 128>>>(xb, Wg, bg, comb);

    cudaMemsetAsync(ffb, 0, (size_t)MM * DD * sizeof(float));

    // ---- MoE: per expert, gathered up-proj then scattered down-proj
    for (int e = 0; e < NE; e++) {
        gemm_mma<2, true><<<gF, gblk, GSMEM_BYTES>>>(
            xh, xl, w1th + (size_t)e * DD * FFD, w1tl + (size_t)e * DD * FFD,
            b1 + (size_t)e * FFD, nullptr, lstp + e * MM, cntp + e, nullptr,
            nullptr, hh, hl, MM, FFD, DD);
        gemm_mma<3, false><<<gD, gblk, GSMEM_BYTES>>>(
            hh, hl, w2th + (size_t)e * DD * FFD, w2tl + (size_t)e * DD * FFD,
            b2 + (size_t)e * DD, nullptr, lstp + e * MM, cntp + e, comb + e,
            ffb, nullptr, nullptr, MM, DD, FFD);
    }

    // ---- LN2
    ln_kernel<<<MM, 256>>>(xb, ffb, ln2g, ln2b, out, nullptr, nullptr);
}

// round 13
// speedup vs baseline: 3.9829x; 1.3529x over previous
#include <cuda_runtime.h>
#include <cuda_bf16.h>
#include <math.h>

// Problem constants
#define BB 2
#define TT 1024
#define DD 768
#define HH 12
#define HD 64
#define MM (BB*TT)     // 2048
#define FFD 3072
#define NE 4
#define BH (BB*HH)     // 24

typedef __nv_bfloat16 bf16;

// ================= static scratch (no runtime alloc) =================
#define OFF_RES1 0
#define OFF_X    (OFF_RES1 + MM*DD)
#define OFF_FF   (OFF_X    + MM*DD)
#define OFF_COMB (OFF_FF   + MM*DD)
#define OFF_LOG  (OFF_COMB + MM*NE)
#define F32_TOTAL (OFF_LOG + (size_t)BH*TT*TT)
__device__ __align__(256) float g_f32[F32_TOTAL];

#define BO_SRCH 0
#define BO_SRCL (BO_SRCH + MM*DD)
#define BO_AH   (BO_SRCL + MM*DD)
#define BO_AL   (BO_AH   + MM*DD)
#define BO_XH   (BO_AL   + MM*DD)
#define BO_XL   (BO_XH   + MM*DD)
#define BO_HH   (BO_XL   + MM*DD)
#define BO_HL   (BO_HH   + MM*FFD)
#define BO_WQH  (BO_HL   + MM*FFD)
#define BO_WQL  (BO_WQH  + DD*DD)
#define BO_WKH  (BO_WQL  + DD*DD)
#define BO_WKL  (BO_WKH  + DD*DD)
#define BO_WVH  (BO_WKL  + DD*DD)
#define BO_WVL  (BO_WVH  + DD*DD)
#define BO_WOH  (BO_WVL  + DD*DD)
#define BO_WOL  (BO_WOH  + DD*DD)
#define BO_W1TH (BO_WOL  + DD*DD)
#define BO_W1TL (BO_W1TH + NE*DD*FFD)
#define BO_W2TH (BO_W1TL + NE*DD*FFD)
#define BO_W2TL (BO_W2TH + NE*DD*FFD)
#define BO_QH   (BO_W2TL + NE*DD*FFD)
#define BO_KH   (BO_QH   + MM*DD)
#define BO_VT   (BO_KH   + MM*DD)
#define BO_P    (BO_VT   + MM*DD)
#define BF_TOTAL (BO_P + (size_t)BH*TT*TT)
__device__ __align__(256) bf16 g_bf[BF_TOTAL];

__device__ int g_cnt[NE];
__device__ int g_lst[NE * MM];

// ================= PTX helpers =================
__device__ __forceinline__ unsigned smem_u32(const void* p) {
    unsigned a;
    asm("{ .reg .u64 t; cvta.to.shared.u64 t, %1; cvt.u32.u64 %0, t; }" : "=r"(a) : "l"(p));
    return a;
}

#define CP_ASYNC16(sm, gp) \
    asm volatile("cp.async.cg.shared.global [%0], [%1], 16;" :: "r"(sm), "l"(gp))
#define CP_COMMIT() asm volatile("cp.async.commit_group;" ::: "memory")
#define CP_WAIT(n)  asm volatile("cp.async.wait_group %0;" :: "n"(n) : "memory")

#define LDMATRIX_X4(r0, r1, r2, r3, addr) \
    asm volatile("ldmatrix.sync.aligned.m8n8.x4.shared.b16 {%0,%1,%2,%3}, [%4];" \
        : "=r"(r0), "=r"(r1), "=r"(r2), "=r"(r3) : "r"(addr))

#define MMA_BF16(d, a, b0, b1) \
    asm volatile("mma.sync.aligned.m16n8k16.row.col.f32.bf16.bf16.f32 " \
        "{%0,%1,%2,%3}, {%4,%5,%6,%7}, {%8,%9}, {%0,%1,%2,%3};" \
        : "+f"((d)[0]), "+f"((d)[1]), "+f"((d)[2]), "+f"((d)[3]) \
        : "r"((a)[0]), "r"((a)[1]), "r"((a)[2]), "r"((a)[3]), "r"(b0), "r"(b1))

__device__ __forceinline__ void split2(float x, bf16& h, bf16& l) {
    h = __float2bfloat16_rn(x);
    l = __float2bfloat16_rn(x - __bfloat162float(h));
}

// ================= reductions =================
__device__ __forceinline__ float blk_reduce_sum(float v, float* red) {
    int tid = threadIdx.x;
    red[tid] = v; __syncthreads();
    for (int s = blockDim.x >> 1; s > 0; s >>= 1) {
        if (tid < s) red[tid] += red[tid + s];
        __syncthreads();
    }
    float r = red[0]; __syncthreads();
    return r;
}
__device__ __forceinline__ float blk_reduce_max(float v, float* red) {
    int tid = threadIdx.x;
    red[tid] = v; __syncthreads();
    for (int s = blockDim.x >> 1; s > 0; s >>= 1) {
        if (tid < s) red[tid] = fmaxf(red[tid], red[tid + s]);
        __syncthreads();
    }
    float r = red[0]; __syncthreads();
    return r;
}

// ================= split-bf16 GEMM via mma.sync (HMMA) =================
// C[M,N] = epi( A @ B^T ), A = Ah+Al, B = Bh+Bl (bf16 hi/lo, K-major rows)
// 3 products: (Ah,Bh), (Ah,Bl), (Al,Bh) accumulated in fp32.
// MODE 0: Cf = acc + bias
// MODE 1: Cf = acc + bias + resid          (O-proj)
// MODE 2: relu(acc+bias) -> split bf16 Chh/Chl, compacted rows (MoE up)
// MODE 3: Cf[gidx[r]] += rw[gidx[r]*NE]*(acc+bias)             (MoE down)
// MODE 4: head-major bf16 emit (Q/K)  Chh[(b*HH+h)*TT + t][64]
// MODE 5: transposed bf16 emit (V)    Chh[(b*HH+h)*64 + d][TT]
#define BM 128
#define BN 128
#define BKC 64
#define NSTAGE 4
#define STAGEB (2 * BM * BKC * 2)           // A tile + B tile = 32768 B
#define GSMEM_BYTES (1024 + 1024 + NSTAGE * STAGEB)

template<int MODE, bool GATHERA>
__global__ __launch_bounds__(256)
void gemm_mma(const bf16* __restrict__ Ah, const bf16* __restrict__ Al,
              const bf16* __restrict__ Bh, const bf16* __restrict__ Bl,
              const float* __restrict__ bias, const float* __restrict__ resid,
              const int* __restrict__ gidx, const int* __restrict__ cntp,
              const float* __restrict__ rw,
              float* __restrict__ Cf, bf16* __restrict__ Chh, bf16* __restrict__ Chl,
              int Mtot, int Ng, int K)
{
    const int tid = threadIdx.x;
    const int lane = tid & 31;
    const int wid = tid >> 5;
    const int wrow = (wid & 1) * 64;
    const int wcol = (wid >> 1) * 32;
    const int col0 = blockIdx.x * BN;
    const int row0 = blockIdx.y * BM;

    int cnt = Mtot;
    if (MODE == 2 || MODE == 3 || GATHERA) {
        cnt = *cntp;
        if (cnt == 0 || row0 >= cnt) return;
    }

    extern __shared__ char rawsm[];
    unsigned rawb = smem_u32(rawsm);
    unsigned base = (rawb + 1023u) & ~1023u;
    char* smp = rawsm + (base - rawb);
    int* idxs = (int*)smp;
    unsigned stg = base + 1024;
    float* stag = (float*)(smp + 1024);

    if ((GATHERA || MODE == 3) && tid < BM) {
        int r = row0 + tid;
        idxs[tid] = gidx[r < cnt ? r : (cnt - 1)];
    }
    __syncthreads();

    const int nck = K / BKC;
    const int NC = 3 * nck;

    float d[4][4][4];
    #pragma unroll
    for (int mf = 0; mf < 4; mf++)
        #pragma unroll
        for (int nf = 0; nf < 4; nf++)
            #pragma unroll
            for (int i = 0; i < 4; i++) d[mf][nf][i] = 0.f;

    auto issue = [&](int c) {
        int p = c / nck, kc = c - p * nck, k0 = kc * BKC;
        const bf16* Asrc = (p == 2) ? Al : Ah;
        const bf16* Bsrc = (p == 1) ? Bl : Bh;
        unsigned sb = stg + (c % NSTAGE) * STAGEB;
        #pragma unroll
        for (int it = 0; it < 4; it++) {
            int u = tid + it * 256;
            int row = u >> 3, seg = u & 7;
            int ar = GATHERA ? idxs[row] : (row0 + row);
            const bf16* gp = Asrc + (size_t)ar * K + k0 + seg * 8;
            unsigned off = row * 128 + seg * 16;
            off ^= (off >> 3) & 0x70;
            CP_ASYNC16(sb + off, gp);
        }
        #pragma unroll
        for (int it = 0; it < 4; it++) {
            int u = tid + it * 256;
            int row = u >> 3, seg = u & 7;
            const bf16* gp = Bsrc + (size_t)(col0 + row) * K + k0 + seg * 8;
            unsigned off = row * 128 + seg * 16;
            off ^= (off >> 3) & 0x70;
            CP_ASYNC16(sb + 16384 + off, gp);
        }
    };

    for (int s = 0; s < NSTAGE - 1; s++) { issue(s); CP_COMMIT(); }

    for (int c = 0; c < NC; c++) {
        CP_WAIT(NSTAGE - 2);
        __syncthreads();
        if (c + NSTAGE - 1 < NC) issue(c + NSTAGE - 1);
        CP_COMMIT();

        unsigned Ab = stg + (c % NSTAGE) * STAGEB;
        unsigned Bb = Ab + 16384;
        #pragma unroll
        for (int ks = 0; ks < 4; ks++) {
            const int kb = ks * 32;
            unsigned a[4][4];
            #pragma unroll
            for (int mf = 0; mf < 4; mf++) {
                int row = wrow + mf * 16 + ((lane >> 3) & 1) * 8 + (lane & 7);
                int cb = kb + (lane >> 4) * 16;
                unsigned ad = Ab + row * 128 + (cb ^ ((row & 7) << 4));
                LDMATRIX_X4(a[mf][0], a[mf][1], a[mf][2], a[mf][3], ad);
            }
            unsigned bq[2][4];
            #pragma unroll
            for (int g = 0; g < 2; g++) {
                int row = wcol + g * 16 + (lane >> 4) * 8 + (lane & 7);
                int cb = kb + ((lane >> 3) & 1) * 16;
                unsigned ad = Bb + row * 128 + (cb ^ ((row & 7) << 4));
                LDMATRIX_X4(bq[g][0], bq[g][1], bq[g][2], bq[g][3], ad);
            }
            #pragma unroll
            for (int mf = 0; mf < 4; mf++)
                #pragma unroll
                for (int nf = 0; nf < 4; nf++)
                    MMA_BF16(d[mf][nf], a[mf], bq[nf >> 1][(nf & 1) * 2],
                             bq[nf >> 1][(nf & 1) * 2 + 1]);
        }
    }
    __syncthreads();

    #pragma unroll
    for (int mf = 0; mf < 4; mf++)
        #pragma unroll
        for (int nf = 0; nf < 4; nf++) {
            int r = wrow + mf * 16 + (lane >> 2);
            int cc = wcol + nf * 8 + (lane & 3) * 2;
            *(float2*)&stag[r * 132 + cc] = make_float2(d[mf][nf][0], d[mf][nf][1]);
            *(float2*)&stag[(r + 8) * 132 + cc] = make_float2(d[mf][nf][2], d[mf][nf][3]);
        }
    __syncthreads();

    #pragma unroll 4
    for (int i = 0; i < 16; i++) {
        int flat = i * 256 + tid;
        int row = flat >> 5;
        int seg = flat & 31;
        if ((MODE == 2 || MODE == 3) && (row0 + row >= cnt)) continue;
        int gc = col0 + seg * 4;
        float4 bi = *(const float4*)&bias[gc];
        float v0 = stag[row * 132 + seg * 4 + 0] + bi.x;
        float v1 = stag[row * 132 + seg * 4 + 1] + bi.y;
        float v2 = stag[row * 132 + seg * 4 + 2] + bi.z;
        float v3 = stag[row * 132 + seg * 4 + 3] + bi.w;

        if (MODE == 0 || MODE == 1) {
            size_t idx = (size_t)(row0 + row) * Ng + gc;
            if (MODE == 1) {
                float4 rs = *(const float4*)&resid[idx];
                v0 += rs.x; v1 += rs.y; v2 += rs.z; v3 += rs.w;
            }
            *(float4*)&Cf[idx] = make_float4(v0, v1, v2, v3);
        } else if (MODE == 2) {
            v0 = fmaxf(v0, 0.f); v1 = fmaxf(v1, 0.f);
            v2 = fmaxf(v2, 0.f); v3 = fmaxf(v3, 0.f);
            bf16 h4[4] __align__(8), l4[4] __align__(8);
            split2(v0, h4[0], l4[0]); split2(v1, h4[1], l4[1]);
            split2(v2, h4[2], l4[2]); split2(v3, h4[3], l4[3]);
            size_t idx = (size_t)(row0 + row) * Ng + gc;
            *(uint2*)&Chh[idx] = *(uint2*)h4;
            *(uint2*)&Chl[idx] = *(uint2*)l4;
        } else if (MODE == 3) {
            int grow = idxs[row];
            float w = rw[(size_t)grow * NE];
            size_t idx = (size_t)grow * Ng + gc;
            float4 p = *(float4*)&Cf[idx];
            p.x += w * v0; p.y += w * v1; p.z += w * v2; p.w += w * v3;
            *(float4*)&Cf[idx] = p;
        } else if (MODE == 4) {       // Q/K head-major bf16
            int r = row0 + row;
            int b = r / TT, t = r - b * TT;
            int h = gc >> 6, d0 = gc & 63;
            bf16 q4[4] __align__(8);
            q4[0] = __float2bfloat16_rn(v0); q4[1] = __float2bfloat16_rn(v1);
            q4[2] = __float2bfloat16_rn(v2); q4[3] = __float2bfloat16_rn(v3);
            *(uint2*)&Chh[((size_t)(b * HH + h) * TT + t) * HD + d0] = *(uint2*)q4;
        } else {                      // MODE 5: V transposed bf16
            int r = row0 + row;
            int b = r / TT, t = r - b * TT;
            int h = gc >> 6, d0 = gc & 63;
            size_t bi2 = ((size_t)(b * HH + h) * HD + d0) * TT + t;
            Chh[bi2]          = __float2bfloat16_rn(v0);
            Chh[bi2 + TT]     = __float2bfloat16_rn(v1);
            Chh[bi2 + 2 * TT] = __float2bfloat16_rn(v2);
            Chh[bi2 + 3 * TT] = __float2bfloat16_rn(v3);
        }
    }
}

// ================= attention: QK^T via mma (K-dim = 64, single chunk) ======
// grid: (k-tile 8, q-tile 8, bh 24). logits raw (unscaled; 1/8 applied in softmax)
__global__ __launch_bounds__(256)
void qk_kernel(const bf16* __restrict__ qh, const bf16* __restrict__ kh,
               float* __restrict__ logits)
{
    __shared__ __align__(1024) char sm[2 * 16384];
    unsigned sbase = smem_u32(sm);
    const int tid = threadIdx.x, lane = tid & 31, wid = tid >> 5;
    const int wrow = (wid & 1) * 64, wcol = (wid >> 1) * 32;
    const int k0 = blockIdx.x * 128, q0 = blockIdx.y * 128, bh = blockIdx.z;
    const bf16* A  = qh + (size_t)bh * TT * HD;
    const bf16* Bm = kh + (size_t)bh * TT * HD;

    #pragma unroll
    for (int it = 0; it < 4; it++) {
        int u = tid + it * 256;
        int row = u >> 3, seg = u & 7;
        unsigned off = row * 128 + seg * 16;
        off ^= (off >> 3) & 0x70;
        CP_ASYNC16(sbase + off, A + (size_t)(q0 + row) * HD + seg * 8);
        CP_ASYNC16(sbase + 16384 + off, Bm + (size_t)(k0 + row) * HD + seg * 8);
    }
    CP_COMMIT(); CP_WAIT(0);
    __syncthreads();

    float d[4][4][4] = {};
    #pragma unroll
    for (int ks = 0; ks < 4; ks++) {
        const int kb = ks * 32;
        unsigned a[4][4];
        #pragma unroll
        for (int mf = 0; mf < 4; mf++) {
            int row = wrow + mf * 16 + ((lane >> 3) & 1) * 8 + (lane & 7);
            int cb = kb + (lane >> 4) * 16;
            unsigned ad = sbase + row * 128 + (cb ^ ((row & 7) << 4));
            LDMATRIX_X4(a[mf][0], a[mf][1], a[mf][2], a[mf][3], ad);
        }
        unsigned bq[2][4];
        #pragma unroll
        for (int g = 0; g < 2; g++) {
            int row = wcol + g * 16 + (lane >> 4) * 8 + (lane & 7);
            int cb = kb + ((lane >> 3) & 1) * 16;
            unsigned ad = sbase + 16384 + row * 128 + (cb ^ ((row & 7) << 4));
            LDMATRIX_X4(bq[g][0], bq[g][1], bq[g][2], bq[g][3], ad);
        }
        #pragma unroll
        for (int mf = 0; mf < 4; mf++)
            #pragma unroll
            for (int nf = 0; nf < 4; nf++)
                MMA_BF16(d[mf][nf], a[mf], bq[nf >> 1][(nf & 1) * 2],
                         bq[nf >> 1][(nf & 1) * 2 + 1]);
    }

    float* lp = logits + (size_t)bh * TT * TT;
    #pragma unroll
    for (int mf = 0; mf < 4; mf++)
        #pragma unroll
        for (int nf = 0; nf < 4; nf++) {
            int r = wrow + mf * 16 + (lane >> 2);
            int cc = wcol + nf * 8 + (lane & 3) * 2;
            *(float2*)&lp[(size_t)(q0 + r) * TT + k0 + cc] =
                make_float2(d[mf][nf][0], d[mf][nf][1]);
            *(float2*)&lp[(size_t)(q0 + r + 8) * TT + k0 + cc] =
                make_float2(d[mf][nf][2], d[mf][nf][3]);
        }
}

// ================= softmax row: zscore(ddof=1, eps-on-std) -> P bf16 =======
__global__ __launch_bounds__(256)
void softmax_kernel(const float* __restrict__ logits, const float* __restrict__ gamma_p,
                    bf16* __restrict__ pbuf)
{
    __shared__ float red[256];
    const size_t row = blockIdx.x;
    const int tid = threadIdx.x;
    float4 v = *(const float4*)&logits[row * TT + tid * 4];
    float l0 = v.x * 0.125f, l1 = v.y * 0.125f, l2 = v.z * 0.125f, l3 = v.w * 0.125f;

    float s = blk_reduce_sum(l0 + l1 + l2 + l3, red);
    float s2 = blk_reduce_sum(l0*l0 + l1*l1 + l2*l2 + l3*l3, red);
    float mean = s * (1.0f / TT);
    float var = (s2 - (float)TT * mean * mean) * (1.0f / (TT - 1));
    var = fmaxf(var, 0.0f);
    float a = (*gamma_p) / (sqrtf(var) + 1e-5f);

    float z0 = a * (l0 - mean), z1 = a * (l1 - mean);
    float z2 = a * (l2 - mean), z3 = a * (l3 - mean);
    float mx = blk_reduce_max(fmaxf(fmaxf(z0, z1), fmaxf(z2, z3)), red);
    float e0 = __expf(z0 - mx), e1 = __expf(z1 - mx);
    float e2 = __expf(z2 - mx), e3 = __expf(z3 - mx);
    float Z = blk_reduce_sum(e0 + e1 + e2 + e3, red);
    float rz = 1.0f / Z;
    bf16 p4[4] __align__(8);
    p4[0] = __float2bfloat16_rn(e0 * rz); p4[1] = __float2bfloat16_rn(e1 * rz);
    p4[2] = __float2bfloat16_rn(e2 * rz); p4[3] = __float2bfloat16_rn(e3 * rz);
    *(uint2*)&pbuf[row * TT + tid * 4] = *(uint2*)p4;
}

// ================= PV: P[1024,1024] @ Vt[64,1024]^T via mma ================
// grid: (q-tile 8, bh 24). Emits split bf16 ah/al in [M, DD] layout.
#define PV_STAGEB (16384 + 8192)
#define PV_SMEM_BYTES (1024 + 3 * PV_STAGEB)

__global__ __launch_bounds__(256)
void pv_kernel(const bf16* __restrict__ pbuf, const bf16* __restrict__ vt,
               bf16* __restrict__ oh, bf16* __restrict__ ol)
{
    extern __shared__ char pvraw[];
    unsigned rawb = smem_u32(pvraw);
    unsigned stg = (rawb + 1023u) & ~1023u;

    const int tid = threadIdx.x, lane = tid & 31, wid = tid >> 5;
    const int wrow = (wid & 1) * 64, wcol = (wid >> 1) * 16;
    const int row0 = blockIdx.x * 128, bh = blockIdx.y;
    const int b = bh / HH, h = bh - b * HH;
    const bf16* A  = pbuf + (size_t)bh * TT * TT;
    const bf16* Bm = vt + (size_t)bh * HD * TT;

    auto issue = [&](int c) {
        int k0 = c * BKC;
        unsigned sb = stg + (c % 3) * PV_STAGEB;
        #pragma unroll
        for (int it = 0; it < 4; it++) {
            int u = tid + it * 256;
            int row = u >> 3, seg = u & 7;
            unsigned off = row * 128 + seg * 16;
            off ^= (off >> 3) & 0x70;
            CP_ASYNC16(sb + off, A + (size_t)(row0 + row) * TT + k0 + seg * 8);
        }
        #pragma unroll
        for (int it = 0; it < 2; it++) {
            int u = tid + it * 256;
            int row = u >> 3, seg = u & 7;
            unsigned off = row * 128 + seg * 16;
            off ^= (off >> 3) & 0x70;
            CP_ASYNC16(sb + 16384 + off, Bm + (size_t)row * TT + k0 + seg * 8);
        }
    };

    float d[4][2][4];
    #pragma unroll
    for (int mf = 0; mf < 4; mf++)
        #pragma unroll
        for (int nf = 0; nf < 2; nf++)
            #pragma unroll
            for (int i = 0; i < 4; i++) d[mf][nf][i] = 0.f;

    const int NC = TT / BKC;  // 16
    for (int s = 0; s < 2; s++) { issue(s); CP_COMMIT(); }

    for (int c = 0; c < NC; c++) {
        CP_WAIT(1);
        __syncthreads();
        if (c + 2 < NC) issue(c + 2);
        CP_COMMIT();

        unsigned Ab = stg + (c % 3) * PV_STAGEB;
        unsigned Bb = Ab + 16384;
        #pragma unroll
        for (int ks = 0; ks < 4; ks++) {
            const int kb = ks * 32;
            unsigned a[4][4];
            #pragma unroll
            for (int mf = 0; mf < 4; mf++) {
                int row = wrow + mf * 16 + ((lane >> 3) & 1) * 8 + (lane & 7);
                int cb = kb + (lane >> 4) * 16;
                unsigned ad = Ab + row * 128 + (cb ^ ((row & 7) << 4));
                LDMATRIX_X4(a[mf][0], a[mf][1], a[mf][2], a[mf][3], ad);
            }
            unsigned bqv[4];
            {
                int row = wcol + (lane >> 4) * 8 + (lane & 7);
                int cb = kb + ((lane >> 3) & 1) * 16;
                unsigned ad = Bb + row * 128 + (cb ^ ((row & 7) << 4));
                LDMATRIX_X4(bqv[0], bqv[1], bqv[2], bqv[3], ad);
            }
            #pragma unroll
            for (int mf = 0; mf < 4; mf++)
                #pragma unroll
                for (int nf = 0; nf < 2; nf++)
                    MMA_BF16(d[mf][nf], a[mf], bqv[nf * 2], bqv[nf * 2 + 1]);
        }
    }

    // epilogue: split-bf16 emit into [M, DD] (for O-proj)
    #pragma unroll
    for (int mf = 0; mf < 4; mf++)
        #pragma unroll
        for (int nf = 0; nf < 2; nf++) {
            int r = wrow + mf * 16 + (lane >> 2);
            int cc = wcol + nf * 8 + (lane & 3) * 2;
            #pragma unroll
            for (int half = 0; half < 2; half++) {
                int q = row0 + r + half * 8;
                float x0 = d[mf][nf][half * 2 + 0];
                float x1 = d[mf][nf][half * 2 + 1];
                bf16 h0, l0, h1, l1;
                split2(x0, h0, l0); split2(x1, h1, l1);
                size_t idx = ((size_t)(b * TT + q)) * DD + h * HD + cc;
                __nv_bfloat162 hv; hv.x = h0; hv.y = h1;
                __nv_bfloat162 lv; lv.x = l0; lv.y = l1;
                *(__nv_bfloat162*)&oh[idx] = hv;
                *(__nv_bfloat162*)&ol[idx] = lv;
            }
        }
}

// ================= layernorm (optional bf16 hi/lo emit) =================
__global__ __launch_bounds__(256)
void ln_kernel(const float* __restrict__ in, const float* __restrict__ add,
               const float* __restrict__ gw, const float* __restrict__ bw,
               float* __restrict__ out, bf16* __restrict__ oh, bf16* __restrict__ ol)
{
    const int row = blockIdx.x;
    const int tid = threadIdx.x;
    __shared__ float red[256];

    float v[3];
    #pragma unroll
    for (int i = 0; i < 3; i++) {
        int c = tid + i * 256;
        size_t idx = (size_t)row * DD + c;
        v[i] = in[idx] + (add ? add[idx] : 0.0f);
    }
    float tot = blk_reduce_sum(v[0] + v[1] + v[2], red);
    float mean = tot * (1.0f / DD);
    float s2 = 0.f;
    #pragma unroll
    for (int i = 0; i < 3; i++) { float dd = v[i] - mean; s2 += dd * dd; }
    float var = blk_reduce_sum(s2, red) * (1.0f / DD);
    float rstd = rsqrtf(var + 1e-5f);
    #pragma unroll
    for (int i = 0; i < 3; i++) {
        int c = tid + i * 256;
        size_t idx = (size_t)row * DD + c;
        float y = (v[i] - mean) * rstd * gw[c] + bw[c];
        out[idx] = y;
        if (oh) { bf16 hh, ll; split2(y, hh, ll); oh[idx] = hh; ol[idx] = ll; }
    }
}

// ================= conversions =================
__global__ __launch_bounds__(256)
void split_kernel(const float* __restrict__ in, bf16* __restrict__ oh,
                  bf16* __restrict__ ol, int n4)
{
    int i = blockIdx.x * 256 + threadIdx.x;
    if (i >= n4) return;
    float4 v = *(const float4*)&in[i * 4];
    bf16 h4[4] __align__(8), l4[4] __align__(8);
    split2(v.x, h4[0], l4[0]); split2(v.y, h4[1], l4[1]);
    split2(v.z, h4[2], l4[2]); split2(v.w, h4[3], l4[3]);
    *(uint2*)&oh[i * 4] = *(uint2*)h4;
    *(uint2*)&ol[i * 4] = *(uint2*)l4;
}

__global__ __launch_bounds__(256)
void tsplit_kernel(const float* __restrict__ in, bf16* __restrict__ oh,
                   bf16* __restrict__ ol, int Kd, int Nd)
{
    __shared__ float t[32][33];
    int e = blockIdx.z;
    const float* ip = in + (size_t)e * Kd * Nd;
    bf16* hp = oh + (size_t)e * Kd * Nd;
    bf16* lp = ol + (size_t)e * Kd * Nd;
    int n0 = blockIdx.x * 32, k0 = blockIdx.y * 32;
    int tx = threadIdx.x, ty = threadIdx.y;
    #pragma unroll
    for (int r = 0; r < 4; r++)
        t[ty + 8 * r][tx] = ip[(size_t)(k0 + ty + 8 * r) * Nd + n0 + tx];
    __syncthreads();
    #pragma unroll
    for (int r = 0; r < 4; r++) {
        float v = t[tx][ty + 8 * r];
        bf16 hh, ll; split2(v, hh, ll);
        size_t idx = (size_t)(n0 + ty + 8 * r) * Kd + k0 + tx;
        hp[idx] = hh; lp[idx] = ll;
    }
}

// ================= counters / gate =================
__global__ void zero_cnt_kernel() {
    if (threadIdx.x < NE) g_cnt[threadIdx.x] = 0;
}

__global__ __launch_bounds__(128)
void gate_kernel(const float* __restrict__ x, const float* __restrict__ Wg,
                 const float* __restrict__ bg, float* __restrict__ comb)
{
    const int row = blockIdx.x;
    const int tid = threadIdx.x;
    float acc[NE] = {};
    for (int d = tid; d < DD; d += 128) {
        float xv = x[(size_t)row * DD + d];
        #pragma unroll
        for (int e = 0; e < NE; e++) acc[e] += xv * Wg[e * DD + d];
    }
    __shared__ float red[NE][128];
    #pragma unroll
    for (int e = 0; e < NE; e++) red[e][tid] = acc[e];
    __syncthreads();
    for (int s = 64; s > 0; s >>= 1) {
        if (tid < s) {
            #pragma unroll
            for (int e = 0; e < NE; e++) red[e][tid] += red[e][tid + s];
        }
        __syncthreads();
    }
    if (tid == 0) {
        float sc[NE];
        #pragma unroll
        for (int e = 0; e < NE; e++) sc[e] = red[e][0] + bg[e];
        float m = sc[0];
        #pragma unroll
        for (int e = 1; e < NE; e++) m = fmaxf(m, sc[e]);
        float p[NE], Z = 0.f;
        #pragma unroll
        for (int e = 0; e < NE; e++) { p[e] = __expf(sc[e] - m); Z += p[e]; }
        #pragma unroll
        for (int e = 0; e < NE; e++) p[e] /= Z;
        int i1 = 0;
        for (int e = 1; e < NE; e++) if (p[e] > p[i1]) i1 = e;
        int i2 = -1;
        for (int e = 0; e < NE; e++) {
            if (e == i1) continue;
            if (i2 < 0 || p[e] > p[i2]) i2 = e;
        }
        #pragma unroll
        for (int e = 0; e < NE; e++)
            comb[(size_t)row * NE + e] = (e == i1 || e == i2) ? p[e] : 0.0f;
        int p1 = atomicAdd(&g_cnt[i1], 1);
        g_lst[i1 * MM + p1] = row;
        int p2 = atomicAdd(&g_cnt[i2], 1);
        g_lst[i2 * MM + p2] = row;
    }
}

// ================= launcher =================
extern "C" void kernel_launch(void* const* d_in, const int* in_sizes, int n_in,
                              void* d_out, int out_size)
{
    (void)in_sizes; (void)n_in; (void)out_size;
    const float* src   = (const float*)d_in[0];
    const float* Wq    = (const float*)d_in[2];
    const float* bq    = (const float*)d_in[3];
    const float* Wk    = (const float*)d_in[4];
    const float* bk    = (const float*)d_in[5];
    const float* Wv    = (const float*)d_in[6];
    const float* bv    = (const float*)d_in[7];
    const float* Wo    = (const float*)d_in[8];
    const float* bo    = (const float*)d_in[9];
    const float* gamma = (const float*)d_in[10];
    const float* ln1g  = (const float*)d_in[11];
    const float* ln1b  = (const float*)d_in[12];
    const float* ln2g  = (const float*)d_in[13];
    const float* ln2b  = (const float*)d_in[14];
    const float* Wg    = (const float*)d_in[15];
    const float* bg    = (const float*)d_in[16];
    const float* W1    = (const float*)d_in[17];
    const float* b1    = (const float*)d_in[18];
    const float* W2    = (const float*)d_in[19];
    const float* b2    = (const float*)d_in[20];
    float* out = (float*)d_out;

    float* fb = nullptr; cudaGetSymbolAddress((void**)&fb, g_f32);
    bf16*  bb = nullptr; cudaGetSymbolAddress((void**)&bb, g_bf);
    int* cntp = nullptr; cudaGetSymbolAddress((void**)&cntp, g_cnt);
    int* lstp = nullptr; cudaGetSymbolAddress((void**)&lstp, g_lst);

    float* res1   = fb + OFF_RES1;
    float* xb     = fb + OFF_X;
    float* ffb    = fb + OFF_FF;
    float* comb   = fb + OFF_COMB;
    float* logits = fb + OFF_LOG;

    bf16 *srch = bb + BO_SRCH, *srcl = bb + BO_SRCL;
    bf16 *ah   = bb + BO_AH,   *al   = bb + BO_AL;
    bf16 *xh   = bb + BO_XH,   *xl   = bb + BO_XL;
    bf16 *hh   = bb + BO_HH,   *hl   = bb + BO_HL;
    bf16 *wqh  = bb + BO_WQH,  *wql  = bb + BO_WQL;
    bf16 *wkh  = bb + BO_WKH,  *wkl  = bb + BO_WKL;
    bf16 *wvh  = bb + BO_WVH,  *wvl  = bb + BO_WVL;
    bf16 *woh  = bb + BO_WOH,  *wol  = bb + BO_WOL;
    bf16 *w1th = bb + BO_W1TH, *w1tl = bb + BO_W1TL;
    bf16 *w2th = bb + BO_W2TH, *w2tl = bb + BO_W2TL;
    bf16 *qh   = bb + BO_QH,   *kh   = bb + BO_KH;
    bf16 *vt   = bb + BO_VT,   *pbuf = bb + BO_P;

    static bool attrs_set = false;
    if (!attrs_set) {
        cudaFuncSetAttribute(gemm_mma<0, false>, cudaFuncAttributeMaxDynamicSharedMemorySize, GSMEM_BYTES);
        cudaFuncSetAttribute(gemm_mma<1, false>, cudaFuncAttributeMaxDynamicSharedMemorySize, GSMEM_BYTES);
        cudaFuncSetAttribute(gemm_mma<2, true >, cudaFuncAttributeMaxDynamicSharedMemorySize, GSMEM_BYTES);
        cudaFuncSetAttribute(gemm_mma<3, false>, cudaFuncAttributeMaxDynamicSharedMemorySize, GSMEM_BYTES);
        cudaFuncSetAttribute(gemm_mma<4, false>, cudaFuncAttributeMaxDynamicSharedMemorySize, GSMEM_BYTES);
        cudaFuncSetAttribute(gemm_mma<5, false>, cudaFuncAttributeMaxDynamicSharedMemorySize, GSMEM_BYTES);
        cudaFuncSetAttribute(pv_kernel, cudaFuncAttributeMaxDynamicSharedMemorySize, PV_SMEM_BYTES);
        attrs_set = true;
    }

    // ---- conversions
    split_kernel<<<(MM * DD / 4 + 255) / 256, 256>>>(src, srch, srcl, MM * DD / 4);
    split_kernel<<<(DD * DD / 4 + 255) / 256, 256>>>(Wq, wqh, wql, DD * DD / 4);
    split_kernel<<<(DD * DD / 4 + 255) / 256, 256>>>(Wk, wkh, wkl, DD * DD / 4);
    split_kernel<<<(DD * DD / 4 + 255) / 256, 256>>>(Wv, wvh, wvl, DD * DD / 4);
    split_kernel<<<(DD * DD / 4 + 255) / 256, 256>>>(Wo, woh, wol, DD * DD / 4);
    tsplit_kernel<<<dim3(FFD / 32, DD / 32, NE), dim3(32, 8)>>>(W1, w1th, w1tl, DD, FFD);
    tsplit_kernel<<<dim3(DD / 32, FFD / 32, NE), dim3(32, 8)>>>(W2, w2th, w2tl, FFD, DD);

    zero_cnt_kernel<<<1, 32>>>();

    // ---- QKV projections (HMMA; emit head-major bf16 Q/K and transposed V)
    const dim3 gblk(256);
    const dim3 gD(DD / BN, MM / BM);   // (6,16)
    const dim3 gF(FFD / BN, MM / BM);  // (24,16)
    gemm_mma<4, false><<<gD, gblk, GSMEM_BYTES>>>(srch, srcl, wqh, wql, bq,
        nullptr, nullptr, nullptr, nullptr, nullptr, qh, nullptr, MM, DD, DD);
    gemm_mma<4, false><<<gD, gblk, GSMEM_BYTES>>>(srch, srcl, wkh, wkl, bk,
        nullptr, nullptr, nullptr, nullptr, nullptr, kh, nullptr, MM, DD, DD);
    gemm_mma<5, false><<<gD, gblk, GSMEM_BYTES>>>(srch, srcl, wvh, wvl, bv,
        nullptr, nullptr, nullptr, nullptr, nullptr, vt, nullptr, MM, DD, DD);

    // ---- attention: QK^T -> zscore softmax -> PV (all mma / bulk passes)
    qk_kernel<<<dim3(TT / 128, TT / 128, BH), 256>>>(qh, kh, logits);
    softmax_kernel<<<BH * TT, 256>>>(logits, gamma, pbuf);
    pv_kernel<<<dim3(TT / 128, BH), 256, PV_SMEM_BYTES>>>(pbuf, vt, ah, al);

    // ---- out-proj + residual
    gemm_mma<1, false><<<gD, gblk, GSMEM_BYTES>>>(ah, al, woh, wol, bo,
        src, nullptr, nullptr, nullptr, res1, nullptr, nullptr, MM, DD, DD);

    // ---- LN1 (emits x fp32 + bf16 hi/lo)
    ln_kernel<<<MM, 256>>>(res1, nullptr, ln1g, ln1b, xb, xh, xl);

    // ---- gate
    gate_kernel<<<MM, 128>>>(xb, Wg, bg, comb);

    cudaMemsetAsync(ffb, 0, (size_t)MM * DD * sizeof(float));

    // ---- MoE: per expert, gathered up-proj then scattered down-proj
    for (int e = 0; e < NE; e++) {
        gemm_mma<2, true><<<gF, gblk, GSMEM_BYTES>>>(
            xh, xl, w1th + (size_t)e * DD * FFD, w1tl + (size_t)e * DD * FFD,
            b1 + (size_t)e * FFD, nullptr, lstp + e * MM, cntp + e, nullptr,
            nullptr, hh, hl, MM, FFD, DD);
        gemm_mma<3, false><<<gD, gblk, GSMEM_BYTES>>>(
            hh, hl, w2th + (size_t)e * DD * FFD, w2tl + (size_t)e * DD * FFD,
            b2 + (size_t)e * DD, nullptr, lstp + e * MM, cntp + e, comb + e,
            ffb, nullptr, nullptr, MM, DD, FFD);
    }

    // ---- LN2
    ln_kernel<<<MM, 256>>>(xb, ffb, ln2g, ln2b, out, nullptr, nullptr);
}

// round 15
// speedup vs baseline: 4.6552x; 1.1688x over previous
#include <cuda_runtime.h>
#include <cuda_bf16.h>
#include <math.h>

// Problem constants
#define BB 2
#define TT 1024
#define DD 768
#define HH 12
#define HD 64
#define MM (BB*TT)     // 2048
#define FFD 3072
#define NE 4
#define BH (BB*HH)     // 24

typedef __nv_bfloat16 bf16;

// ================= static scratch (no runtime alloc) =================
#define OFF_RES1 0
#define OFF_X    (OFF_RES1 + MM*DD)
#define OFF_FF   (OFF_X    + MM*DD)
#define OFF_COMB (OFF_FF   + MM*DD)
#define OFF_LOG  (OFF_COMB + MM*NE)
#define F32_TOTAL (OFF_LOG + (size_t)BH*TT*TT)
__device__ __align__(256) float g_f32[F32_TOTAL];

#define BO_SRCH 0
#define BO_SRCL (BO_SRCH + MM*DD)
#define BO_AH   (BO_SRCL + MM*DD)
#define BO_AL   (BO_AH   + MM*DD)
#define BO_XH   (BO_AL   + MM*DD)
#define BO_XL   (BO_XH   + MM*DD)
#define BO_HH   (BO_XL   + MM*DD)
#define BO_HL   (BO_HH   + MM*FFD)
#define BO_WQH  (BO_HL   + MM*FFD)
#define BO_WQL  (BO_WQH  + DD*DD)
#define BO_WKH  (BO_WQL  + DD*DD)
#define BO_WKL  (BO_WKH  + DD*DD)
#define BO_WVH  (BO_WKL  + DD*DD)
#define BO_WVL  (BO_WVH  + DD*DD)
#define BO_WOH  (BO_WVL  + DD*DD)
#define BO_WOL  (BO_WOH  + DD*DD)
#define BO_W1TH (BO_WOL  + DD*DD)
#define BO_W1TL (BO_W1TH + NE*DD*FFD)
#define BO_W2TH (BO_W1TL + NE*DD*FFD)
#define BO_W2TL (BO_W2TH + NE*DD*FFD)
#define BO_QH   (BO_W2TL + NE*DD*FFD)
#define BO_KH   (BO_QH   + MM*DD)
#define BO_VT   (BO_KH   + MM*DD)
#define BO_P    (BO_VT   + MM*DD)
#define BF_TOTAL (BO_P + (size_t)BH*TT*TT)
__device__ __align__(256) bf16 g_bf[BF_TOTAL];

__device__ int g_cnt[NE];
__device__ int g_lst[NE * MM];

// ================= PTX helpers =================
__device__ __forceinline__ unsigned smem_u32(const void* p) {
    unsigned a;
    asm("{ .reg .u64 t; cvta.to.shared.u64 t, %1; cvt.u32.u64 %0, t; }" : "=r"(a) : "l"(p));
    return a;
}

#define CP_ASYNC16(sm, gp) \
    asm volatile("cp.async.cg.shared.global [%0], [%1], 16;" :: "r"(sm), "l"(gp))
#define CP_COMMIT() asm volatile("cp.async.commit_group;" ::: "memory")
#define CP_WAIT(n)  asm volatile("cp.async.wait_group %0;" :: "n"(n) : "memory")

#define LDMATRIX_X4(r0, r1, r2, r3, addr) \
    asm volatile("ldmatrix.sync.aligned.m8n8.x4.shared.b16 {%0,%1,%2,%3}, [%4];" \
        : "=r"(r0), "=r"(r1), "=r"(r2), "=r"(r3) : "r"(addr))

#define MMA_BF16(d, a, b0, b1) \
    asm volatile("mma.sync.aligned.m16n8k16.row.col.f32.bf16.bf16.f32 " \
        "{%0,%1,%2,%3}, {%4,%5,%6,%7}, {%8,%9}, {%0,%1,%2,%3};" \
        : "+f"((d)[0]), "+f"((d)[1]), "+f"((d)[2]), "+f"((d)[3]) \
        : "r"((a)[0]), "r"((a)[1]), "r"((a)[2]), "r"((a)[3]), "r"(b0), "r"(b1))

__device__ __forceinline__ void split2(float x, bf16& h, bf16& l) {
    h = __float2bfloat16_rn(x);
    l = __float2bfloat16_rn(x - __bfloat162float(h));
}

// ================= reductions =================
__device__ __forceinline__ float blk_reduce_sum(float v, float* red) {
    int tid = threadIdx.x;
    red[tid] = v; __syncthreads();
    for (int s = blockDim.x >> 1; s > 0; s >>= 1) {
        if (tid < s) red[tid] += red[tid + s];
        __syncthreads();
    }
    float r = red[0]; __syncthreads();
    return r;
}
__device__ __forceinline__ float blk_reduce_max(float v, float* red) {
    int tid = threadIdx.x;
    red[tid] = v; __syncthreads();
    for (int s = blockDim.x >> 1; s > 0; s >>= 1) {
        if (tid < s) red[tid] = fmaxf(red[tid], red[tid + s]);
        __syncthreads();
    }
    float r = red[0]; __syncthreads();
    return r;
}

// ================= split-bf16 GEMM via mma.sync (merged 3-product) ========
// C[M,N] = epi( A @ B^T ), A = Ah+Al, B = Bh+Bl (bf16 hi/lo, K-major rows)
// Per k-chunk: load Ah/Al/Bh/Bl tiles ONCE; accumulate AhBh + AhBl + AlBh.
// MODE 0: Cf = acc + bias
// MODE 1: Cf = acc + bias + resid          (O-proj)
// MODE 2: relu(acc+bias) -> split bf16 Chh/Chl, compacted rows (MoE up)
// MODE 3: Cf[gidx[r]] += rw[gidx[r]*NE]*(acc+bias)             (MoE down)
// MODE 4: head-major bf16 emit (Q/K)
// MODE 5: transposed bf16 emit (V)
#define BM 128
#define BN 128
#define BKC 64
#define NSTAGE 3
#define TILEB 16384
#define STAGEB (4 * TILEB)                  // Ah+Al+Bh+Bl = 65536 B
#define GSMEM_BYTES (1024 + 1024 + NSTAGE * STAGEB)

template<int MODE, bool GATHERA>
__global__ __launch_bounds__(256)
void gemm_mma(const bf16* __restrict__ Ah, const bf16* __restrict__ Al,
              const bf16* __restrict__ Bh, const bf16* __restrict__ Bl,
              const float* __restrict__ bias, const float* __restrict__ resid,
              const int* __restrict__ gidx, const int* __restrict__ cntp,
              const float* __restrict__ rw,
              float* __restrict__ Cf, bf16* __restrict__ Chh, bf16* __restrict__ Chl,
              int Mtot, int Ng, int K)
{
    const int tid = threadIdx.x;
    const int lane = tid & 31;
    const int wid = tid >> 5;
    const int wrow = (wid & 1) * 64;
    const int wcol = (wid >> 1) * 32;
    const int col0 = blockIdx.x * BN;
    const int row0 = blockIdx.y * BM;

    int cnt = Mtot;
    if (MODE == 2 || MODE == 3 || GATHERA) {
        cnt = *cntp;
        if (cnt == 0 || row0 >= cnt) return;
    }

    extern __shared__ char rawsm[];
    unsigned rawb = smem_u32(rawsm);
    unsigned base = (rawb + 1023u) & ~1023u;
    char* smp = rawsm + (base - rawb);
    int* idxs = (int*)smp;
    unsigned stg = base + 1024;
    float* stag = (float*)(smp + 1024);

    if ((GATHERA || MODE == 3) && tid < BM) {
        int r = row0 + tid;
        idxs[tid] = gidx[r < cnt ? r : (cnt - 1)];
    }
    __syncthreads();

    const int NC = K / BKC;

    float d[4][4][4];
    #pragma unroll
    for (int mf = 0; mf < 4; mf++)
        #pragma unroll
        for (int nf = 0; nf < 4; nf++)
            #pragma unroll
            for (int i = 0; i < 4; i++) d[mf][nf][i] = 0.f;

    // load all 4 tiles (Ah, Al, Bh, Bl) for k-chunk c
    auto issue = [&](int c) {
        int k0 = c * BKC;
        unsigned sb = stg + (c % NSTAGE) * STAGEB;
        #pragma unroll
        for (int it = 0; it < 4; it++) {
            int u = tid + it * 256;
            int row = u >> 3, seg = u & 7;
            int ar = GATHERA ? idxs[row] : (row0 + row);
            unsigned off = row * 128 + seg * 16;
            off ^= (off >> 3) & 0x70;
            CP_ASYNC16(sb + off,            Ah + (size_t)ar * K + k0 + seg * 8);
            CP_ASYNC16(sb + TILEB + off,    Al + (size_t)ar * K + k0 + seg * 8);
        }
        #pragma unroll
        for (int it = 0; it < 4; it++) {
            int u = tid + it * 256;
            int row = u >> 3, seg = u & 7;
            const bf16* gh = Bh + (size_t)(col0 + row) * K + k0 + seg * 8;
            const bf16* gl = Bl + (size_t)(col0 + row) * K + k0 + seg * 8;
            unsigned off = row * 128 + seg * 16;
            off ^= (off >> 3) & 0x70;
            CP_ASYNC16(sb + 2 * TILEB + off, gh);
            CP_ASYNC16(sb + 3 * TILEB + off, gl);
        }
    };

    for (int s = 0; s < NSTAGE - 1; s++) { issue(s); CP_COMMIT(); }

    for (int c = 0; c < NC; c++) {
        CP_WAIT(NSTAGE - 2);
        __syncthreads();
        if (c + NSTAGE - 1 < NC) issue(c + NSTAGE - 1);
        CP_COMMIT();   // unconditional: keeps wait_group counting exact at tail

        unsigned Sb = stg + (c % NSTAGE) * STAGEB;
        #pragma unroll
        for (int ks = 0; ks < 4; ks++) {
            const int kb = ks * 32;
            unsigned ah_[4][4], al_[4][4];
            #pragma unroll
            for (int mf = 0; mf < 4; mf++) {
                int row = wrow + mf * 16 + ((lane >> 3) & 1) * 8 + (lane & 7);
                int cb = kb + (lane >> 4) * 16;
                unsigned sw = row * 128 + (cb ^ ((row & 7) << 4));
                LDMATRIX_X4(ah_[mf][0], ah_[mf][1], ah_[mf][2], ah_[mf][3], Sb + sw);
                LDMATRIX_X4(al_[mf][0], al_[mf][1], al_[mf][2], al_[mf][3], Sb + TILEB + sw);
            }
            unsigned bh_[2][4], bl_[2][4];
            #pragma unroll
            for (int g = 0; g < 2; g++) {
                int row = wcol + g * 16 + (lane >> 4) * 8 + (lane & 7);
                int cb = kb + ((lane >> 3) & 1) * 16;
                unsigned sw = row * 128 + (cb ^ ((row & 7) << 4));
                LDMATRIX_X4(bh_[g][0], bh_[g][1], bh_[g][2], bh_[g][3], Sb + 2 * TILEB + sw);
                LDMATRIX_X4(bl_[g][0], bl_[g][1], bl_[g][2], bl_[g][3], Sb + 3 * TILEB + sw);
            }
            #pragma unroll
            for (int mf = 0; mf < 4; mf++)
                #pragma unroll
                for (int nf = 0; nf < 4; nf++) {
                    unsigned h0 = bh_[nf >> 1][(nf & 1) * 2], h1 = bh_[nf >> 1][(nf & 1) * 2 + 1];
                    unsigned l0 = bl_[nf >> 1][(nf & 1) * 2], l1 = bl_[nf >> 1][(nf & 1) * 2 + 1];
                    MMA_BF16(d[mf][nf], ah_[mf], h0, h1);
                    MMA_BF16(d[mf][nf], ah_[mf], l0, l1);
                    MMA_BF16(d[mf][nf], al_[mf], h0, h1);
                }
        }
    }
    __syncthreads();

    #pragma unroll
    for (int mf = 0; mf < 4; mf++)
        #pragma unroll
        for (int nf = 0; nf < 4; nf++) {
            int r = wrow + mf * 16 + (lane >> 2);
            int cc = wcol + nf * 8 + (lane & 3) * 2;
            *(float2*)&stag[r * 132 + cc] = make_float2(d[mf][nf][0], d[mf][nf][1]);
            *(float2*)&stag[(r + 8) * 132 + cc] = make_float2(d[mf][nf][2], d[mf][nf][3]);
        }
    __syncthreads();

    #pragma unroll 4
    for (int i = 0; i < 16; i++) {
        int flat = i * 256 + tid;
        int row = flat >> 5;
        int seg = flat & 31;
        if ((MODE == 2 || MODE == 3) && (row0 + row >= cnt)) continue;
        int gc = col0 + seg * 4;
        float4 bi = *(const float4*)&bias[gc];
        float v0 = stag[row * 132 + seg * 4 + 0] + bi.x;
        float v1 = stag[row * 132 + seg * 4 + 1] + bi.y;
        float v2 = stag[row * 132 + seg * 4 + 2] + bi.z;
        float v3 = stag[row * 132 + seg * 4 + 3] + bi.w;

        if (MODE == 0 || MODE == 1) {
            size_t idx = (size_t)(row0 + row) * Ng + gc;
            if (MODE == 1) {
                float4 rs = *(const float4*)&resid[idx];
                v0 += rs.x; v1 += rs.y; v2 += rs.z; v3 += rs.w;
            }
            *(float4*)&Cf[idx] = make_float4(v0, v1, v2, v3);
        } else if (MODE == 2) {
            v0 = fmaxf(v0, 0.f); v1 = fmaxf(v1, 0.f);
            v2 = fmaxf(v2, 0.f); v3 = fmaxf(v3, 0.f);
            bf16 h4[4] __align__(8), l4[4] __align__(8);
            split2(v0, h4[0], l4[0]); split2(v1, h4[1], l4[1]);
            split2(v2, h4[2], l4[2]); split2(v3, h4[3], l4[3]);
            size_t idx = (size_t)(row0 + row) * Ng + gc;
            *(uint2*)&Chh[idx] = *(uint2*)h4;
            *(uint2*)&Chl[idx] = *(uint2*)l4;
        } else if (MODE == 3) {
            int grow = idxs[row];
            float w = rw[(size_t)grow * NE];
            size_t idx = (size_t)grow * Ng + gc;
            float4 p = *(float4*)&Cf[idx];
            p.x += w * v0; p.y += w * v1; p.z += w * v2; p.w += w * v3;
            *(float4*)&Cf[idx] = p;
        } else if (MODE == 4) {       // Q/K head-major bf16
            int r = row0 + row;
            int b = r / TT, t = r - b * TT;
            int h = gc >> 6, d0 = gc & 63;
            bf16 q4[4] __align__(8);
            q4[0] = __float2bfloat16_rn(v0); q4[1] = __float2bfloat16_rn(v1);
            q4[2] = __float2bfloat16_rn(v2); q4[3] = __float2bfloat16_rn(v3);
            *(uint2*)&Chh[((size_t)(b * HH + h) * TT + t) * HD + d0] = *(uint2*)q4;
        } else {                      // MODE 5: V transposed bf16
            int r = row0 + row;
            int b = r / TT, t = r - b * TT;
            int h = gc >> 6, d0 = gc & 63;
            size_t bi2 = ((size_t)(b * HH + h) * HD + d0) * TT + t;
            Chh[bi2]          = __float2bfloat16_rn(v0);
            Chh[bi2 + TT]     = __float2bfloat16_rn(v1);
            Chh[bi2 + 2 * TT] = __float2bfloat16_rn(v2);
            Chh[bi2 + 3 * TT] = __float2bfloat16_rn(v3);
        }
    }
}

// ================= attention: QK^T via mma (K-dim = 64, single chunk) ======
__global__ __launch_bounds__(256)
void qk_kernel(const bf16* __restrict__ qh, const bf16* __restrict__ kh,
               float* __restrict__ logits)
{
    __shared__ __align__(1024) char sm[2 * 16384];
    unsigned sbase = smem_u32(sm);
    const int tid = threadIdx.x, lane = tid & 31, wid = tid >> 5;
    const int wrow = (wid & 1) * 64, wcol = (wid >> 1) * 32;
    const int k0 = blockIdx.x * 128, q0 = blockIdx.y * 128, bh = blockIdx.z;
    const bf16* A  = qh + (size_t)bh * TT * HD;
    const bf16* Bm = kh + (size_t)bh * TT * HD;

    #pragma unroll
    for (int it = 0; it < 4; it++) {
        int u = tid + it * 256;
        int row = u >> 3, seg = u & 7;
        unsigned off = row * 128 + seg * 16;
        off ^= (off >> 3) & 0x70;
        CP_ASYNC16(sbase + off, A + (size_t)(q0 + row) * HD + seg * 8);
        CP_ASYNC16(sbase + 16384 + off, Bm + (size_t)(k0 + row) * HD + seg * 8);
    }
    CP_COMMIT(); CP_WAIT(0);
    __syncthreads();

    float d[4][4][4] = {};
    #pragma unroll
    for (int ks = 0; ks < 4; ks++) {
        const int kb = ks * 32;
        unsigned a[4][4];
        #pragma unroll
        for (int mf = 0; mf < 4; mf++) {
            int row = wrow + mf * 16 + ((lane >> 3) & 1) * 8 + (lane & 7);
            int cb = kb + (lane >> 4) * 16;
            unsigned ad = sbase + row * 128 + (cb ^ ((row & 7) << 4));
            LDMATRIX_X4(a[mf][0], a[mf][1], a[mf][2], a[mf][3], ad);
        }
        unsigned bq[2][4];
        #pragma unroll
        for (int g = 0; g < 2; g++) {
            int row = wcol + g * 16 + (lane >> 4) * 8 + (lane & 7);
            int cb = kb + ((lane >> 3) & 1) * 16;
            unsigned ad = sbase + 16384 + row * 128 + (cb ^ ((row & 7) << 4));
            LDMATRIX_X4(bq[g][0], bq[g][1], bq[g][2], bq[g][3], ad);
        }
        #pragma unroll
        for (int mf = 0; mf < 4; mf++)
            #pragma unroll
            for (int nf = 0; nf < 4; nf++)
                MMA_BF16(d[mf][nf], a[mf], bq[nf >> 1][(nf & 1) * 2],
                         bq[nf >> 1][(nf & 1) * 2 + 1]);
    }

    float* lp = logits + (size_t)bh * TT * TT;
    #pragma unroll
    for (int mf = 0; mf < 4; mf++)
        #pragma unroll
        for (int nf = 0; nf < 4; nf++) {
            int r = wrow + mf * 16 + (lane >> 2);
            int cc = wcol + nf * 8 + (lane & 3) * 2;
            *(float2*)&lp[(size_t)(q0 + r) * TT + k0 + cc] =
                make_float2(d[mf][nf][0], d[mf][nf][1]);
            *(float2*)&lp[(size_t)(q0 + r + 8) * TT + k0 + cc] =
                make_float2(d[mf][nf][2], d[mf][nf][3]);
        }
}

// ================= softmax row: zscore(ddof=1, eps-on-std) -> P bf16 =======
__global__ __launch_bounds__(256)
void softmax_kernel(const float* __restrict__ logits, const float* __restrict__ gamma_p,
                    bf16* __restrict__ pbuf)
{
    __shared__ float red[256];
    const size_t row = blockIdx.x;
    const int tid = threadIdx.x;
    float4 v = *(const float4*)&logits[row * TT + tid * 4];
    float l0 = v.x * 0.125f, l1 = v.y * 0.125f, l2 = v.z * 0.125f, l3 = v.w * 0.125f;

    float s = blk_reduce_sum(l0 + l1 + l2 + l3, red);
    float s2 = blk_reduce_sum(l0*l0 + l1*l1 + l2*l2 + l3*l3, red);
    float mean = s * (1.0f / TT);
    float var = (s2 - (float)TT * mean * mean) * (1.0f / (TT - 1));
    var = fmaxf(var, 0.0f);
    float a = (*gamma_p) / (sqrtf(var) + 1e-5f);

    float z0 = a * (l0 - mean), z1 = a * (l1 - mean);
    float z2 = a * (l2 - mean), z3 = a * (l3 - mean);
    float mx = blk_reduce_max(fmaxf(fmaxf(z0, z1), fmaxf(z2, z3)), red);
    float e0 = __expf(z0 - mx), e1 = __expf(z1 - mx);
    float e2 = __expf(z2 - mx), e3 = __expf(z3 - mx);
    float Z = blk_reduce_sum(e0 + e1 + e2 + e3, red);
    float rz = 1.0f / Z;
    bf16 p4[4] __align__(8);
    p4[0] = __float2bfloat16_rn(e0 * rz); p4[1] = __float2bfloat16_rn(e1 * rz);
    p4[2] = __float2bfloat16_rn(e2 * rz); p4[3] = __float2bfloat16_rn(e3 * rz);
    *(uint2*)&pbuf[row * TT + tid * 4] = *(uint2*)p4;
}

// ================= PV: P[1024,1024] @ Vt[64,1024]^T via mma ================
#define PV_STAGEB (16384 + 8192)
#define PV_SMEM_BYTES (1024 + 3 * PV_STAGEB)

__global__ __launch_bounds__(256)
void pv_kernel(const bf16* __restrict__ pbuf, const bf16* __restrict__ vt,
               bf16* __restrict__ oh, bf16* __restrict__ ol)
{
    extern __shared__ char pvraw[];
    unsigned rawb = smem_u32(pvraw);
    unsigned stg = (rawb + 1023u) & ~1023u;

    const int tid = threadIdx.x, lane = tid & 31, wid = tid >> 5;
    const int wrow = (wid & 1) * 64, wcol = (wid >> 1) * 16;
    const int row0 = blockIdx.x * 128, bh = blockIdx.y;
    const int b = bh / HH, h = bh - b * HH;
    const bf16* A  = pbuf + (size_t)bh * TT * TT;
    const bf16* Bm = vt + (size_t)bh * HD * TT;

    auto issue = [&](int c) {
        int k0 = c * BKC;
        unsigned sb = stg + (c % 3) * PV_STAGEB;
        #pragma unroll
        for (int it = 0; it < 4; it++) {
            int u = tid + it * 256;
            int row = u >> 3, seg = u & 7;
            unsigned off = row * 128 + seg * 16;
            off ^= (off >> 3) & 0x70;
            CP_ASYNC16(sb + off, A + (size_t)(row0 + row) * TT + k0 + seg * 8);
        }
        #pragma unroll
        for (int it = 0; it < 2; it++) {
            int u = tid + it * 256;
            int row = u >> 3, seg = u & 7;
            unsigned off = row * 128 + seg * 16;
            off ^= (off >> 3) & 0x70;
            CP_ASYNC16(sb + 16384 + off, Bm + (size_t)row * TT + k0 + seg * 8);
        }
    };

    float d[4][2][4];
    #pragma unroll
    for (int mf = 0; mf < 4; mf++)
        #pragma unroll
        for (int nf = 0; nf < 2; nf++)
            #pragma unroll
            for (int i = 0; i < 4; i++) d[mf][nf][i] = 0.f;

    const int NC = TT / BKC;  // 16
    for (int s = 0; s < 2; s++) { issue(s); CP_COMMIT(); }

    for (int c = 0; c < NC; c++) {
        CP_WAIT(1);
        __syncthreads();
        if (c + 2 < NC) issue(c + 2);
        CP_COMMIT();

        unsigned Ab = stg + (c % 3) * PV_STAGEB;
        unsigned Bb = Ab + 16384;
        #pragma unroll
        for (int ks = 0; ks < 4; ks++) {
            const int kb = ks * 32;
            unsigned a[4][4];
            #pragma unroll
            for (int mf = 0; mf < 4; mf++) {
                int row = wrow + mf * 16 + ((lane >> 3) & 1) * 8 + (lane & 7);
                int cb = kb + (lane >> 4) * 16;
                unsigned ad = Ab + row * 128 + (cb ^ ((row & 7) << 4));
                LDMATRIX_X4(a[mf][0], a[mf][1], a[mf][2], a[mf][3], ad);
            }
            unsigned bqv[4];
            {
                int row = wcol + (lane >> 4) * 8 + (lane & 7);
                int cb = kb + ((lane >> 3) & 1) * 16;
                unsigned ad = Bb + row * 128 + (cb ^ ((row & 7) << 4));
                LDMATRIX_X4(bqv[0], bqv[1], bqv[2], bqv[3], ad);
            }
            #pragma unroll
            for (int mf = 0; mf < 4; mf++)
                #pragma unroll
                for (int nf = 0; nf < 2; nf++)
                    MMA_BF16(d[mf][nf], a[mf], bqv[nf * 2], bqv[nf * 2 + 1]);
        }
    }

    #pragma unroll
    for (int mf = 0; mf < 4; mf++)
        #pragma unroll
        for (int nf = 0; nf < 2; nf++) {
            int r = wrow + mf * 16 + (lane >> 2);
            int cc = wcol + nf * 8 + (lane & 3) * 2;
            #pragma unroll
            for (int half = 0; half < 2; half++) {
                int q = row0 + r + half * 8;
                float x0 = d[mf][nf][half * 2 + 0];
                float x1 = d[mf][nf][half * 2 + 1];
                bf16 h0, l0, h1, l1;
                split2(x0, h0, l0); split2(x1, h1, l1);
                size_t idx = ((size_t)(b * TT + q)) * DD + h * HD + cc;
                __nv_bfloat162 hv; hv.x = h0; hv.y = h1;
                __nv_bfloat162 lv; lv.x = l0; lv.y = l1;
                *(__nv_bfloat162*)&oh[idx] = hv;
                *(__nv_bfloat162*)&ol[idx] = lv;
            }
        }
}

// ================= layernorm (optional bf16 hi/lo emit) =================
__global__ __launch_bounds__(256)
void ln_kernel(const float* __restrict__ in, const float* __restrict__ add,
               const float* __restrict__ gw, const float* __restrict__ bw,
               float* __restrict__ out, bf16* __restrict__ oh, bf16* __restrict__ ol)
{
    const int row = blockIdx.x;
    const int tid = threadIdx.x;
    __shared__ float red[256];

    float v[3];
    #pragma unroll
    for (int i = 0; i < 3; i++) {
        int c = tid + i * 256;
        size_t idx = (size_t)row * DD + c;
        v[i] = in[idx] + (add ? add[idx] : 0.0f);
    }
    float tot = blk_reduce_sum(v[0] + v[1] + v[2], red);
    float mean = tot * (1.0f / DD);
    float s2 = 0.f;
    #pragma unroll
    for (int i = 0; i < 3; i++) { float dd = v[i] - mean; s2 += dd * dd; }
    float var = blk_reduce_sum(s2, red) * (1.0f / DD);
    float rstd = rsqrtf(var + 1e-5f);
    #pragma unroll
    for (int i = 0; i < 3; i++) {
        int c = tid + i * 256;
        size_t idx = (size_t)row * DD + c;
        float y = (v[i] - mean) * rstd * gw[c] + bw[c];
        out[idx] = y;
        if (oh) { bf16 hh, ll; split2(y, hh, ll); oh[idx] = hh; ol[idx] = ll; }
    }
}

// ================= conversions =================
__global__ __launch_bounds__(256)
void split_kernel(const float* __restrict__ in, bf16* __restrict__ oh,
                  bf16* __restrict__ ol, int n4)
{
    int i = blockIdx.x * 256 + threadIdx.x;
    if (i >= n4) return;
    float4 v = *(const float4*)&in[i * 4];
    bf16 h4[4] __align__(8), l4[4] __align__(8);
    split2(v.x, h4[0], l4[0]); split2(v.y, h4[1], l4[1]);
    split2(v.z, h4[2], l4[2]); split2(v.w, h4[3], l4[3]);
    *(uint2*)&oh[i * 4] = *(uint2*)h4;
    *(uint2*)&ol[i * 4] = *(uint2*)l4;
}

__global__ __launch_bounds__(256)
void tsplit_kernel(const float* __restrict__ in, bf16* __restrict__ oh,
                   bf16* __restrict__ ol, int Kd, int Nd)
{
    __shared__ float t[32][33];
    int e = blockIdx.z;
    const float* ip = in + (size_t)e * Kd * Nd;
    bf16* hp = oh + (size_t)e * Kd * Nd;
    bf16* lp = ol + (size_t)e * Kd * Nd;
    int n0 = blockIdx.x * 32, k0 = blockIdx.y * 32;
    int tx = threadIdx.x, ty = threadIdx.y;
    #pragma unroll
    for (int r = 0; r < 4; r++)
        t[ty + 8 * r][tx] = ip[(size_t)(k0 + ty + 8 * r) * Nd + n0 + tx];
    __syncthreads();
    #pragma unroll
    for (int r = 0; r < 4; r++) {
        float v = t[tx][ty + 8 * r];
        bf16 hh, ll; split2(v, hh, ll);
        size_t idx = (size_t)(n0 + ty + 8 * r) * Kd + k0 + tx;
        hp[idx] = hh; lp[idx] = ll;
    }
}

// ================= counters / gate =================
__global__ void zero_cnt_kernel() {
    if (threadIdx.x < NE) g_cnt[threadIdx.x] = 0;
}

__global__ __launch_bounds__(128)
void gate_kernel(const float* __restrict__ x, const float* __restrict__ Wg,
                 const float* __restrict__ bg, float* __restrict__ comb)
{
    const int row = blockIdx.x;
    const int tid = threadIdx.x;
    float acc[NE] = {};
    for (int d = tid; d < DD; d += 128) {
        float xv = x[(size_t)row * DD + d];
        #pragma unroll
        for (int e = 0; e < NE; e++) acc[e] += xv * Wg[e * DD + d];
    }
    __shared__ float red[NE][128];
    #pragma unroll
    for (int e = 0; e < NE; e++) red[e][tid] = acc[e];
    __syncthreads();
    for (int s = 64; s > 0; s >>= 1) {
        if (tid < s) {
            #pragma unroll
            for (int e = 0; e < NE; e++) red[e][tid] += red[e][tid + s];
        }
        __syncthreads();
    }
    if (tid == 0) {
        float sc[NE];
        #pragma unroll
        for (int e = 0; e < NE; e++) sc[e] = red[e][0] + bg[e];
        float m = sc[0];
        #pragma unroll
        for (int e = 1; e < NE; e++) m = fmaxf(m, sc[e]);
        float p[NE], Z = 0.f;
        #pragma unroll
        for (int e = 0; e < NE; e++) { p[e] = __expf(sc[e] - m); Z += p[e]; }
        #pragma unroll
        for (int e = 0; e < NE; e++) p[e] /= Z;
        int i1 = 0;
        for (int e = 1; e < NE; e++) if (p[e] > p[i1]) i1 = e;
        int i2 = -1;
        for (int e = 0; e < NE; e++) {
            if (e == i1) continue;
            if (i2 < 0 || p[e] > p[i2]) i2 = e;
        }
        #pragma unroll
        for (int e = 0; e < NE; e++)
            comb[(size_t)row * NE + e] = (e == i1 || e == i2) ? p[e] : 0.0f;
        int p1 = atomicAdd(&g_cnt[i1], 1);
        g_lst[i1 * MM + p1] = row;
        int p2 = atomicAdd(&g_cnt[i2], 1);
        g_lst[i2 * MM + p2] = row;
    }
}

// ================= launcher =================
extern "C" void kernel_launch(void* const* d_in, const int* in_sizes, int n_in,
                              void* d_out, int out_size)
{
    (void)in_sizes; (void)n_in; (void)out_size;
    const float* src   = (const float*)d_in[0];
    const float* Wq    = (const float*)d_in[2];
    const float* bq    = (const float*)d_in[3];
    const float* Wk    = (const float*)d_in[4];
    const float* bk    = (const float*)d_in[5];
    const float* Wv    = (const float*)d_in[6];
    const float* bv    = (const float*)d_in[7];
    const float* Wo    = (const float*)d_in[8];
    const float* bo    = (const float*)d_in[9];
    const float* gamma = (const float*)d_in[10];
    const float* ln1g  = (const float*)d_in[11];
    const float* ln1b  = (const float*)d_in[12];
    const float* ln2g  = (const float*)d_in[13];
    const float* ln2b  = (const float*)d_in[14];
    const float* Wg    = (const float*)d_in[15];
    const float* bg    = (const float*)d_in[16];
    const float* W1    = (const float*)d_in[17];
    const float* b1    = (const float*)d_in[18];
    const float* W2    = (const float*)d_in[19];
    const float* b2    = (const float*)d_in[20];
    float* out = (float*)d_out;

    float* fb = nullptr; cudaGetSymbolAddress((void**)&fb, g_f32);
    bf16*  bb = nullptr; cudaGetSymbolAddress((void**)&bb, g_bf);
    int* cntp = nullptr; cudaGetSymbolAddress((void**)&cntp, g_cnt);
    int* lstp = nullptr; cudaGetSymbolAddress((void**)&lstp, g_lst);

    float* res1   = fb + OFF_RES1;
    float* xb     = fb + OFF_X;
    float* ffb    = fb + OFF_FF;
    float* comb   = fb + OFF_COMB;
    float* logits = fb + OFF_LOG;

    bf16 *srch = bb + BO_SRCH, *srcl = bb + BO_SRCL;
    bf16 *ah   = bb + BO_AH,   *al   = bb + BO_AL;
    bf16 *xh   = bb + BO_XH,   *xl   = bb + BO_XL;
    bf16 *hh   = bb + BO_HH,   *hl   = bb + BO_HL;
    bf16 *wqh  = bb + BO_WQH,  *wql  = bb + BO_WQL;
    bf16 *wkh  = bb + BO_WKH,  *wkl  = bb + BO_WKL;
    bf16 *wvh  = bb + BO_WVH,  *wvl  = bb + BO_WVL;
    bf16 *woh  = bb + BO_WOH,  *wol  = bb + BO_WOL;
    bf16 *w1th = bb + BO_W1TH, *w1tl = bb + BO_W1TL;
    bf16 *w2th = bb + BO_W2TH, *w2tl = bb + BO_W2TL;
    bf16 *qh   = bb + BO_QH,   *kh   = bb + BO_KH;
    bf16 *vt   = bb + BO_VT,   *pbuf = bb + BO_P;

    static bool attrs_set = false;
    if (!attrs_set) {
        cudaFuncSetAttribute(gemm_mma<0, false>, cudaFuncAttributeMaxDynamicSharedMemorySize, GSMEM_BYTES);
        cudaFuncSetAttribute(gemm_mma<1, false>, cudaFuncAttributeMaxDynamicSharedMemorySize, GSMEM_BYTES);
        cudaFuncSetAttribute(gemm_mma<2, true >, cudaFuncAttributeMaxDynamicSharedMemorySize, GSMEM_BYTES);
        cudaFuncSetAttribute(gemm_mma<3, false>, cudaFuncAttributeMaxDynamicSharedMemorySize, GSMEM_BYTES);
        cudaFuncSetAttribute(gemm_mma<4, false>, cudaFuncAttributeMaxDynamicSharedMemorySize, GSMEM_BYTES);
        cudaFuncSetAttribute(gemm_mma<5, false>, cudaFuncAttributeMaxDynamicSharedMemorySize, GSMEM_BYTES);
        cudaFuncSetAttribute(pv_kernel, cudaFuncAttributeMaxDynamicSharedMemorySize, PV_SMEM_BYTES);
        attrs_set = true;
    }

    const dim3 gblk(256);
    const dim3 gD(DD / BN, MM / BM);   // (6,16)
    const dim3 gF(FFD / BN, MM / BM);  // (24,16)

    // ---- conversions needed for QKV first (gemm launches land in ncu window)
    split_kernel<<<(MM * DD / 4 + 255) / 256, 256>>>(src, srch, srcl, MM * DD / 4);
    split_kernel<<<(DD * DD / 4 + 255) / 256, 256>>>(Wq, wqh, wql, DD * DD / 4);
    split_kernel<<<(DD * DD / 4 + 255) / 256, 256>>>(Wk, wkh, wkl, DD * DD / 4);
    split_kernel<<<(DD * DD / 4 + 255) / 256, 256>>>(Wv, wvh, wvl, DD * DD / 4);

    // ---- QKV projections (merged-product HMMA; head-major Q/K, transposed V)
    gemm_mma<4, false><<<gD, gblk, GSMEM_BYTES>>>(srch, srcl, wqh, wql, bq,
        nullptr, nullptr, nullptr, nullptr, nullptr, qh, nullptr, MM, DD, DD);
    gemm_mma<4, false><<<gD, gblk, GSMEM_BYTES>>>(srch, srcl, wkh, wkl, bk,
        nullptr, nullptr, nullptr, nullptr, nullptr, kh, nullptr, MM, DD, DD);
    gemm_mma<5, false><<<gD, gblk, GSMEM_BYTES>>>(srch, srcl, wvh, wvl, bv,
        nullptr, nullptr, nullptr, nullptr, nullptr, vt, nullptr, MM, DD, DD);

    // ---- remaining conversions (overlap-ready; only needed later)
    split_kernel<<<(DD * DD / 4 + 255) / 256, 256>>>(Wo, woh, wol, DD * DD / 4);
    tsplit_kernel<<<dim3(FFD / 32, DD / 32, NE), dim3(32, 8)>>>(W1, w1th, w1tl, DD, FFD);
    tsplit_kernel<<<dim3(DD / 32, FFD / 32, NE), dim3(32, 8)>>>(W2, w2th, w2tl, FFD, DD);
    zero_cnt_kernel<<<1, 32>>>();

    // ---- attention: QK^T -> zscore softmax -> PV
    qk_kernel<<<dim3(TT / 128, TT / 128, BH), 256>>>(qh, kh, logits);
    softmax_kernel<<<BH * TT, 256>>>(logits, gamma, pbuf);
    pv_kernel<<<dim3(TT / 128, BH), 256, PV_SMEM_BYTES>>>(pbuf, vt, ah, al);

    // ---- out-proj + residual
    gemm_mma<1, false><<<gD, gblk, GSMEM_BYTES>>>(ah, al, woh, wol, bo,
        src, nullptr, nullptr, nullptr, res1, nullptr, nullptr, MM, DD, DD);

    // ---- LN1 (emits x fp32 + bf16 hi/lo)
    ln_kernel<<<MM, 256>>>(res1, nullptr, ln1g, ln1b, xb, xh, xl);

    // ---- gate
    gate_kernel<<<MM, 128>>>(xb, Wg, bg, comb);

    cudaMemsetAsync(ffb, 0, (size_t)MM * DD * sizeof(float));

    // ---- MoE: per expert, gathered up-proj then scattered down-proj
    for (int e = 0; e < NE; e++) {
        gemm_mma<2, true><<<gF, gblk, GSMEM_BYTES>>>(
            xh, xl, w1th + (size_t)e * DD * FFD, w1tl + (size_t)e * DD * FFD,
            b1 + (size_t)e * FFD, nullptr, lstp + e * MM, cntp + e, nullptr,
            nullptr, hh, hl, MM, FFD, DD);
        gemm_mma<3, false><<<gD, gblk, GSMEM_BYTES>>>(
            hh, hl, w2th + (size_t)e * DD * FFD, w2tl + (size_t)e * DD * FFD,
            b2 + (size_t)e * DD, nullptr, lstp + e * MM, cntp + e, comb + e,
            ffb, nullptr, nullptr, MM, DD, FFD);
    }

    // ---- LN2
    ln_kernel<<<MM, 256>>>(xb, ffb, ln2g, ln2b, out, nullptr, nullptr);
}